// round 2
// baseline (speedup 1.0000x reference)
#include <cuda_runtime.h>
#include <math.h>

#define B_  4
#define L_  2048
#define D_  512
#define H_  8
#define DH_ 64
#define NTOK (B_ * L_)   // 8192

// Scratch (allocation-free rule: __device__ globals). 4 x 16MB = 64MB.
__device__ float g_q[(size_t)B_ * H_ * L_ * DH_];
__device__ float g_k[(size_t)B_ * H_ * L_ * DH_];
__device__ float g_v[(size_t)B_ * H_ * L_ * DH_];
__device__ float g_o[(size_t)B_ * H_ * L_ * DH_];

// ---------------------------------------------------------------------------
// Fused QKV projection: Y[n, j] = sum_d X[n,d] * W[j,d] + bias[j]
// written directly into (B,H,L,DH) head layout.
// 64x64 tile, 256 threads, 4x4 register tile, K-chunk 32.
// ---------------------------------------------------------------------------
__global__ __launch_bounds__(256) void proj_kernel(
    const float* __restrict__ Xq, const float* __restrict__ Xk, const float* __restrict__ Xv,
    const float* __restrict__ Wq, const float* __restrict__ Wk, const float* __restrict__ Wv,
    const float* __restrict__ bq, const float* __restrict__ bk, const float* __restrict__ bv)
{
    __shared__ float As[32][68];
    __shared__ float Ws[32][68];

    const float *X, *W, *bias;
    float* Y;
    if (blockIdx.z == 0)      { X = Xq; W = Wq; bias = bq; Y = g_q; }
    else if (blockIdx.z == 1) { X = Xk; W = Wk; bias = bk; Y = g_k; }
    else                      { X = Xv; W = Wv; bias = bv; Y = g_v; }

    const int t  = threadIdx.x;
    const int tr = t >> 4;
    const int tc = t & 15;
    const int m0 = blockIdx.x * 64;
    const int n0 = blockIdx.y * 64;

    float acc[4][4] = {};

    for (int k0 = 0; k0 < D_; k0 += 32) {
        #pragma unroll
        for (int rep = 0; rep < 2; rep++) {
            int id  = t + rep * 256;
            int row = id >> 3;           // 0..63
            int kg  = (id & 7) << 2;     // 0,4,...,28
            float4 xa = *(const float4*)(X + (size_t)(m0 + row) * D_ + k0 + kg);
            float4 wa = *(const float4*)(W + (size_t)(n0 + row) * D_ + k0 + kg);
            As[kg + 0][row] = xa.x; As[kg + 1][row] = xa.y;
            As[kg + 2][row] = xa.z; As[kg + 3][row] = xa.w;
            Ws[kg + 0][row] = wa.x; Ws[kg + 1][row] = wa.y;
            Ws[kg + 2][row] = wa.z; Ws[kg + 3][row] = wa.w;
        }
        __syncthreads();
        #pragma unroll
        for (int kk = 0; kk < 32; kk++) {
            float4 a4 = *(const float4*)&As[kk][tr << 2];
            float4 b4 = *(const float4*)&Ws[kk][tc << 2];
            float a[4] = {a4.x, a4.y, a4.z, a4.w};
            float b[4] = {b4.x, b4.y, b4.z, b4.w};
            #pragma unroll
            for (int i = 0; i < 4; i++)
                #pragma unroll
                for (int j = 0; j < 4; j++)
                    acc[i][j] = fmaf(a[i], b[j], acc[i][j]);
        }
        __syncthreads();
    }

    #pragma unroll
    for (int i = 0; i < 4; i++) {
        int n  = m0 + (tr << 2) + i;
        int bb = n >> 11;              // n / 2048
        int ll = n & (L_ - 1);
        #pragma unroll
        for (int j = 0; j < 4; j++) {
            int col = n0 + (tc << 2) + j;
            int hh  = col >> 6;
            int dh  = col & 63;
            Y[(((size_t)bb * H_ + hh) * L_ + ll) * DH_ + dh] = acc[i][j] + bias[col];
        }
    }
}

// ---------------------------------------------------------------------------
// Output projection: gathers (B,H,L,DH) -> (B*L, D), GEMM with fc_w, + bias.
// ---------------------------------------------------------------------------
__global__ __launch_bounds__(256) void fc_kernel(
    const float* __restrict__ Wf, const float* __restrict__ bf, float* __restrict__ out)
{
    __shared__ float As[32][68];
    __shared__ float Ws[32][68];

    const int t  = threadIdx.x;
    const int tr = t >> 4;
    const int tc = t & 15;
    const int m0 = blockIdx.x * 64;
    const int n0 = blockIdx.y * 64;

    float acc[4][4] = {};

    for (int k0 = 0; k0 < D_; k0 += 32) {
        #pragma unroll
        for (int rep = 0; rep < 2; rep++) {
            int id  = t + rep * 256;
            int row = id >> 3;
            int kg  = (id & 7) << 2;
            int n   = m0 + row;
            int bb  = n >> 11;
            int ll  = n & (L_ - 1);
            int d   = k0 + kg;
            int hh  = d >> 6;
            int dh  = d & 63;
            float4 xa = *(const float4*)(g_o + (((size_t)bb * H_ + hh) * L_ + ll) * DH_ + dh);
            float4 wa = *(const float4*)(Wf + (size_t)(n0 + row) * D_ + k0 + kg);
            As[kg + 0][row] = xa.x; As[kg + 1][row] = xa.y;
            As[kg + 2][row] = xa.z; As[kg + 3][row] = xa.w;
            Ws[kg + 0][row] = wa.x; Ws[kg + 1][row] = wa.y;
            Ws[kg + 2][row] = wa.z; Ws[kg + 3][row] = wa.w;
        }
        __syncthreads();
        #pragma unroll
        for (int kk = 0; kk < 32; kk++) {
            float4 a4 = *(const float4*)&As[kk][tr << 2];
            float4 b4 = *(const float4*)&Ws[kk][tc << 2];
            float a[4] = {a4.x, a4.y, a4.z, a4.w};
            float b[4] = {b4.x, b4.y, b4.z, b4.w};
            #pragma unroll
            for (int i = 0; i < 4; i++)
                #pragma unroll
                for (int j = 0; j < 4; j++)
                    acc[i][j] = fmaf(a[i], b[j], acc[i][j]);
        }
        __syncthreads();
    }

    #pragma unroll
    for (int i = 0; i < 4; i++) {
        int n = m0 + (tr << 2) + i;
        #pragma unroll
        for (int j = 0; j < 4; j++) {
            int col = n0 + (tc << 2) + j;
            out[(size_t)n * D_ + col] = acc[i][j] + bf[col];
        }
    }
}

// ---------------------------------------------------------------------------
// 4x4 register-tile of dot products over a 64-length K dimension from smem.
// ---------------------------------------------------------------------------
__device__ __forceinline__ void tile_dot(const float* __restrict__ A0, int sA,
                                         const float* __restrict__ B0, int sB,
                                         float acc[4][4])
{
    #pragma unroll
    for (int kk = 0; kk < 64; kk += 4) {
        float a[4][4], b[4][4];
        #pragma unroll
        for (int i = 0; i < 4; i++) {
            float4 v = *(const float4*)(A0 + i * sA + kk);
            a[i][0] = v.x; a[i][1] = v.y; a[i][2] = v.z; a[i][3] = v.w;
        }
        #pragma unroll
        for (int j = 0; j < 4; j++) {
            float4 v = *(const float4*)(B0 + j * sB + kk);
            b[j][0] = v.x; b[j][1] = v.y; b[j][2] = v.z; b[j][3] = v.w;
        }
        #pragma unroll
        for (int i = 0; i < 4; i++)
            #pragma unroll
            for (int j = 0; j < 4; j++)
                #pragma unroll
                for (int c = 0; c < 4; c++)
                    acc[i][j] = fmaf(a[i][c], b[j][c], acc[i][j]);
    }
}

// ---------------------------------------------------------------------------
// Flash-style causal attention with relative position term.
// S[l,m] = (q[l]·k[m] + q[l]·E[L-1-l+m]) / 8, causal softmax, O = P·V.
// Per key tile: QE strip of 128 E-rows computed as two 64x64 GEMMs;
// gather S2[li,mi] = QEb[li][63 - li + mi].
// smem: Qs[64][68] | Bs[64][72] (E/K/V, reused) | QEb[64][132] (cols 0..63
// reused as P after the gather barrier).
// ---------------------------------------------------------------------------
__global__ __launch_bounds__(256) void attn_kernel(const float* __restrict__ E)
{
    extern __shared__ float sm[];
    float* Qs  = sm;                          // 64 x 68
    float* Bs  = sm + 64 * 68;                // 64 x 72
    float* QEb = sm + 64 * 68 + 64 * 72;      // 64 x 132

    const int t  = threadIdx.x;
    const int tr = t >> 4;
    const int tc = t & 15;
    const int qt = (int)(gridDim.x - 1) - (int)blockIdx.x;  // heavy tiles first
    const int l0 = qt * 64;
    const int bh = blockIdx.y;

    const float* qp = g_q + (size_t)bh * L_ * DH_;
    const float* kp = g_k + (size_t)bh * L_ * DH_;
    const float* vp = g_v + (size_t)bh * L_ * DH_;

    // Load Q tile
    #pragma unroll
    for (int r = 0; r < 4; r++) {
        int idx = t + r * 256;            // float4 index, 0..1023
        int row = idx >> 4;
        int col = (idx & 15) << 2;
        *(float4*)&Qs[row * 68 + col] =
            *(const float4*)(qp + (size_t)(l0 + row) * DH_ + col);
    }

    float Ot[4][4] = {};
    float mrow[4], lrow[4];
    #pragma unroll
    for (int i = 0; i < 4; i++) { mrow[i] = -1e30f; lrow[i] = 0.f; }

    const int ntiles = qt + 1;
    for (int tt = 0; tt < ntiles; tt++) {
        const int m0    = tt * 64;
        const int jbase = L_ - 64 - l0 + m0;

        // ---- QE strip: two 64-column halves ----
        #pragma unroll
        for (int half = 0; half < 2; half++) {
            __syncthreads();   // prior consumers of Bs / QEb done
            #pragma unroll
            for (int r = 0; r < 4; r++) {
                int idx = t + r * 256;
                int row = idx >> 4;
                int col = (idx & 15) << 2;
                int er  = jbase + half * 64 + row;
                er = (er < L_) ? er : (L_ - 1);   // OOB rows are masked later
                *(float4*)&Bs[row * 72 + col] =
                    *(const float4*)(E + (size_t)er * DH_ + col);
            }
            __syncthreads();
            float qe[4][4] = {};
            tile_dot(&Qs[(tr << 2) * 68], 68, &Bs[(tc << 2) * 72], 72, qe);
            #pragma unroll
            for (int i = 0; i < 4; i++)
                #pragma unroll
                for (int j = 0; j < 4; j++)
                    QEb[((tr << 2) + i) * 132 + half * 64 + (tc << 2) + j] = qe[i][j];
        }

        // ---- K tile, S = Q K^T + gather(QE) ----
        __syncthreads();
        #pragma unroll
        for (int r = 0; r < 4; r++) {
            int idx = t + r * 256;
            int row = idx >> 4;
            int col = (idx & 15) << 2;
            *(float4*)&Bs[row * 72 + col] =
                *(const float4*)(kp + (size_t)(m0 + row) * DH_ + col);
        }
        __syncthreads();

        float sacc[4][4] = {};
        tile_dot(&Qs[(tr << 2) * 68], 68, &Bs[(tc << 2) * 72], 72, sacc);

        #pragma unroll
        for (int i = 0; i < 4; i++) {
            int li = (tr << 2) + i;
            int l  = l0 + li;
            #pragma unroll
            for (int j = 0; j < 4; j++) {
                int mi = (tc << 2) + j;
                int m  = m0 + mi;
                float sv = (sacc[i][j] + QEb[li * 132 + 63 - li + mi]) * 0.125f;
                sacc[i][j] = (m <= l) ? sv : -1e30f;
            }
        }

        __syncthreads();   // all QEb gathers + K reads complete

        // ---- V tile load (Bs free now) ----
        #pragma unroll
        for (int r = 0; r < 4; r++) {
            int idx = t + r * 256;
            int row = idx >> 4;
            int col = (idx & 15) << 2;
            *(float4*)&Bs[row * 72 + col] =
                *(const float4*)(vp + (size_t)(m0 + row) * DH_ + col);
        }

        // ---- online softmax; write P into QEb cols 0..63 ----
        #pragma unroll
        for (int i = 0; i < 4; i++) {
            float mx = fmaxf(fmaxf(sacc[i][0], sacc[i][1]),
                             fmaxf(sacc[i][2], sacc[i][3]));
            #pragma unroll
            for (int off = 8; off > 0; off >>= 1)
                mx = fmaxf(mx, __shfl_xor_sync(0xffffffffu, mx, off));
            float mnew = fmaxf(mrow[i], mx);
            float corr = __expf(mrow[i] - mnew);
            float psum = 0.f;
            #pragma unroll
            for (int j = 0; j < 4; j++) {
                float p = __expf(sacc[i][j] - mnew);
                QEb[((tr << 2) + i) * 132 + (tc << 2) + j] = p;
                psum += p;
            }
            #pragma unroll
            for (int off = 8; off > 0; off >>= 1)
                psum += __shfl_xor_sync(0xffffffffu, psum, off);
            lrow[i] = lrow[i] * corr + psum;
            mrow[i] = mnew;
            #pragma unroll
            for (int j = 0; j < 4; j++) Ot[i][j] *= corr;
        }

        __syncthreads();   // P + V visible

        // ---- O += P @ V ----
        #pragma unroll
        for (int kk = 0; kk < 64; kk += 4) {
            float p[4][4], vv[4][4];
            #pragma unroll
            for (int i = 0; i < 4; i++) {
                float4 x = *(const float4*)&QEb[((tr << 2) + i) * 132 + kk];
                p[i][0] = x.x; p[i][1] = x.y; p[i][2] = x.z; p[i][3] = x.w;
            }
            #pragma unroll
            for (int mm = 0; mm < 4; mm++) {
                float4 x = *(const float4*)&Bs[(kk + mm) * 72 + (tc << 2)];
                vv[mm][0] = x.x; vv[mm][1] = x.y; vv[mm][2] = x.z; vv[mm][3] = x.w;
            }
            #pragma unroll
            for (int i = 0; i < 4; i++)
                #pragma unroll
                for (int j = 0; j < 4; j++)
                    #pragma unroll
                    for (int mm = 0; mm < 4; mm++)
                        Ot[i][j] = fmaf(p[i][mm], vv[mm][j], Ot[i][j]);
        }
    }

    float* op = g_o + (size_t)bh * L_ * DH_;
    #pragma unroll
    for (int i = 0; i < 4; i++) {
        float inv = 1.0f / lrow[i];
        int row = l0 + (tr << 2) + i;
        #pragma unroll
        for (int j = 0; j < 4; j++)
            op[(size_t)row * DH_ + (tc << 2) + j] = Ot[i][j] * inv;
    }
}

// ---------------------------------------------------------------------------
extern "C" void kernel_launch(void* const* d_in, const int* in_sizes, int n_in,
                              void* d_out, int out_size)
{
    const float* Q  = (const float*)d_in[0];
    const float* K  = (const float*)d_in[1];
    const float* V  = (const float*)d_in[2];
    // d_in[3] = mask (causal, known analytically) - unused
    const float* Wq = (const float*)d_in[4];
    const float* bq = (const float*)d_in[5];
    const float* Wk = (const float*)d_in[6];
    const float* bk = (const float*)d_in[7];
    const float* Wv = (const float*)d_in[8];
    const float* bv = (const float*)d_in[9];
    const float* Wf = (const float*)d_in[10];
    const float* bf = (const float*)d_in[11];
    const float* E  = (const float*)d_in[12];
    // d_in[13] = H (known constant 8) - unused
    float* out = (float*)d_out;

    (void)in_sizes; (void)n_in; (void)out_size;

    dim3 gproj(NTOK / 64, D_ / 64, 3);
    proj_kernel<<<gproj, 256>>>(Q, K, V, Wq, Wk, Wv, bq, bk, bv);

    const int smem_attn = 64 * (68 + 72 + 132) * (int)sizeof(float);  // 69632 B
    cudaFuncSetAttribute(attn_kernel, cudaFuncAttributeMaxDynamicSharedMemorySize,
                         smem_attn);
    dim3 gattn(L_ / 64, B_ * H_);
    attn_kernel<<<gattn, 256, smem_attn>>>(E);

    dim3 gfc(NTOK / 64, D_ / 64);
    fc_kernel<<<gfc, 256>>>(Wf, bf, out);
}

// round 3
// speedup vs baseline: 2.2702x; 2.2702x over previous
#include <cuda_runtime.h>
#include <math.h>

#define B_  4
#define L_  2048
#define D_  512
#define H_  8
#define DH_ 64
#define NTOK (B_ * L_)   // 8192

// Scratch (allocation-free rule: __device__ globals). 4 x 16MB = 64MB.
__device__ float g_q[(size_t)B_ * H_ * L_ * DH_];
__device__ float g_k[(size_t)B_ * H_ * L_ * DH_];
__device__ float g_v[(size_t)B_ * H_ * L_ * DH_];
__device__ float g_o[(size_t)B_ * H_ * L_ * DH_];

// ---------------------------------------------------------------------------
// Fused QKV projection: Y[n, j] = sum_d X[n,d] * W[j,d] + bias[j]
// 128x128 tile, 256 threads, 8x8 register tile (1 B/FMA -> FMA-bound),
// K-chunk 16, transposed smem operands.
// ---------------------------------------------------------------------------
__global__ __launch_bounds__(256) void proj_kernel(
    const float* __restrict__ Xq, const float* __restrict__ Xk, const float* __restrict__ Xv,
    const float* __restrict__ Wq, const float* __restrict__ Wk, const float* __restrict__ Wv,
    const float* __restrict__ bq, const float* __restrict__ bk, const float* __restrict__ bv)
{
    __shared__ float As[16][132];
    __shared__ float Ws[16][132];

    const float *X, *W, *bias;
    float* Y;
    if (blockIdx.z == 0)      { X = Xq; W = Wq; bias = bq; Y = g_q; }
    else if (blockIdx.z == 1) { X = Xk; W = Wk; bias = bk; Y = g_k; }
    else                      { X = Xv; W = Wv; bias = bv; Y = g_v; }

    const int t  = threadIdx.x;
    const int tr = t >> 4;        // 0..15
    const int tc = t & 15;        // 0..15
    const int m0 = blockIdx.x * 128;
    const int n0 = blockIdx.y * 128;

    float acc[8][8] = {};

    for (int k0 = 0; k0 < D_; k0 += 16) {
        #pragma unroll
        for (int rep = 0; rep < 2; rep++) {
            int id  = t + rep * 256;      // 0..511
            int row = id >> 2;            // 0..127
            int kg  = (id & 3) << 2;      // 0,4,8,12
            float4 xa = *(const float4*)(X + (size_t)(m0 + row) * D_ + k0 + kg);
            float4 wa = *(const float4*)(W + (size_t)(n0 + row) * D_ + k0 + kg);
            As[kg + 0][row] = xa.x; As[kg + 1][row] = xa.y;
            As[kg + 2][row] = xa.z; As[kg + 3][row] = xa.w;
            Ws[kg + 0][row] = wa.x; Ws[kg + 1][row] = wa.y;
            Ws[kg + 2][row] = wa.z; Ws[kg + 3][row] = wa.w;
        }
        __syncthreads();
        #pragma unroll
        for (int kk = 0; kk < 16; kk++) {
            float4 a0 = *(const float4*)&As[kk][tr << 2];
            float4 a1 = *(const float4*)&As[kk][64 + (tr << 2)];
            float4 b0 = *(const float4*)&Ws[kk][tc << 2];
            float4 b1 = *(const float4*)&Ws[kk][64 + (tc << 2)];
            float a[8] = {a0.x, a0.y, a0.z, a0.w, a1.x, a1.y, a1.z, a1.w};
            float b[8] = {b0.x, b0.y, b0.z, b0.w, b1.x, b1.y, b1.z, b1.w};
            #pragma unroll
            for (int i = 0; i < 8; i++)
                #pragma unroll
                for (int j = 0; j < 8; j++)
                    acc[i][j] = fmaf(a[i], b[j], acc[i][j]);
        }
        __syncthreads();
    }

    #pragma unroll
    for (int ih = 0; ih < 2; ih++) {
        #pragma unroll
        for (int i = 0; i < 4; i++) {
            int n  = m0 + ih * 64 + (tr << 2) + i;
            int bb = n >> 11;
            int ll = n & (L_ - 1);
            #pragma unroll
            for (int jh = 0; jh < 2; jh++) {
                int col = n0 + jh * 64 + (tc << 2);
                int hh  = col >> 6;
                int dh  = col & 63;
                float4 o;
                o.x = acc[ih * 4 + i][jh * 4 + 0] + bias[col + 0];
                o.y = acc[ih * 4 + i][jh * 4 + 1] + bias[col + 1];
                o.z = acc[ih * 4 + i][jh * 4 + 2] + bias[col + 2];
                o.w = acc[ih * 4 + i][jh * 4 + 3] + bias[col + 3];
                *(float4*)(Y + (((size_t)bb * H_ + hh) * L_ + ll) * DH_ + dh) = o;
            }
        }
    }
}

// ---------------------------------------------------------------------------
// Output projection: gathers (B,H,L,DH) -> (B*L, D), 128x128 tile, 8x8.
// ---------------------------------------------------------------------------
__global__ __launch_bounds__(256) void fc_kernel(
    const float* __restrict__ Wf, const float* __restrict__ bf, float* __restrict__ out)
{
    __shared__ float As[16][132];
    __shared__ float Ws[16][132];

    const int t  = threadIdx.x;
    const int tr = t >> 4;
    const int tc = t & 15;
    const int m0 = blockIdx.x * 128;
    const int n0 = blockIdx.y * 128;

    float acc[8][8] = {};

    for (int k0 = 0; k0 < D_; k0 += 16) {
        #pragma unroll
        for (int rep = 0; rep < 2; rep++) {
            int id  = t + rep * 256;
            int row = id >> 2;
            int kg  = (id & 3) << 2;
            int n   = m0 + row;
            int bb  = n >> 11;
            int ll  = n & (L_ - 1);
            int d   = k0 + kg;
            int hh  = d >> 6;
            int dh  = d & 63;
            float4 xa = *(const float4*)(g_o + (((size_t)bb * H_ + hh) * L_ + ll) * DH_ + dh);
            float4 wa = *(const float4*)(Wf + (size_t)(n0 + row) * D_ + k0 + kg);
            As[kg + 0][row] = xa.x; As[kg + 1][row] = xa.y;
            As[kg + 2][row] = xa.z; As[kg + 3][row] = xa.w;
            Ws[kg + 0][row] = wa.x; Ws[kg + 1][row] = wa.y;
            Ws[kg + 2][row] = wa.z; Ws[kg + 3][row] = wa.w;
        }
        __syncthreads();
        #pragma unroll
        for (int kk = 0; kk < 16; kk++) {
            float4 a0 = *(const float4*)&As[kk][tr << 2];
            float4 a1 = *(const float4*)&As[kk][64 + (tr << 2)];
            float4 b0 = *(const float4*)&Ws[kk][tc << 2];
            float4 b1 = *(const float4*)&Ws[kk][64 + (tc << 2)];
            float a[8] = {a0.x, a0.y, a0.z, a0.w, a1.x, a1.y, a1.z, a1.w};
            float b[8] = {b0.x, b0.y, b0.z, b0.w, b1.x, b1.y, b1.z, b1.w};
            #pragma unroll
            for (int i = 0; i < 8; i++)
                #pragma unroll
                for (int j = 0; j < 8; j++)
                    acc[i][j] = fmaf(a[i], b[j], acc[i][j]);
        }
        __syncthreads();
    }

    #pragma unroll
    for (int ih = 0; ih < 2; ih++) {
        #pragma unroll
        for (int i = 0; i < 4; i++) {
            int n = m0 + ih * 64 + (tr << 2) + i;
            #pragma unroll
            for (int jh = 0; jh < 2; jh++) {
                int col = n0 + jh * 64 + (tc << 2);
                float4 o;
                o.x = acc[ih * 4 + i][jh * 4 + 0] + bf[col + 0];
                o.y = acc[ih * 4 + i][jh * 4 + 1] + bf[col + 1];
                o.z = acc[ih * 4 + i][jh * 4 + 2] + bf[col + 2];
                o.w = acc[ih * 4 + i][jh * 4 + 3] + bf[col + 3];
                *(float4*)(out + (size_t)n * D_ + col) = o;
            }
        }
    }
}

// ---------------------------------------------------------------------------
// 8x4 register-tile dot: acc[i][j] += sum_k A[rowA_i][k] * B[rowB_j][k],
// K = 64 contiguous, both operands row-major with stride 68.
// ---------------------------------------------------------------------------
__device__ __forceinline__ void dot8x4(const float* __restrict__ A0,
                                       const float* __restrict__ B0,
                                       float acc[8][4])
{
    #pragma unroll
    for (int kk = 0; kk < 64; kk += 4) {
        float4 a[8], b[4];
        #pragma unroll
        for (int i = 0; i < 8; i++) a[i] = *(const float4*)(A0 + i * 68 + kk);
        #pragma unroll
        for (int j = 0; j < 4; j++) b[j] = *(const float4*)(B0 + j * 68 + kk);
        #pragma unroll
        for (int i = 0; i < 8; i++)
            #pragma unroll
            for (int j = 0; j < 4; j++) {
                acc[i][j] = fmaf(a[i].x, b[j].x, acc[i][j]);
                acc[i][j] = fmaf(a[i].y, b[j].y, acc[i][j]);
                acc[i][j] = fmaf(a[i].z, b[j].z, acc[i][j]);
                acc[i][j] = fmaf(a[i].w, b[j].w, acc[i][j]);
            }
    }
}

// ---------------------------------------------------------------------------
// Flash-style causal attention with relative-position term.
// S[l,m] = (q[l]·k[m] + q[l]·E[L-1-l+m]) / 8, online softmax, O = P·V.
// QE panel ring cache: each key-tile iteration computes ONE new 64x64 QE
// panel (the previous "hi" panel is reused as the new "lo").
// 128 threads, 8 rows x 4 cols per thread.
// smem: Qs | Bs (E/K/V) | Pan[2] | Ps  = 5 * 64*68 floats = 87,040 B.
// ---------------------------------------------------------------------------
__global__ __launch_bounds__(128) void attn_kernel(const float* __restrict__ E)
{
    extern __shared__ float sm[];
    float* Qs   = sm;                 // 64 x 68
    float* Bs   = sm + 4352;          // 64 x 68 (E / K / V, serial reuse)
    float* PanA = sm + 2 * 4352;      // 64 x 68
    float* PanB = sm + 3 * 4352;      // 64 x 68
    float* Ps   = sm + 4 * 4352;      // 64 x 68

    const int t  = threadIdx.x;
    const int tr = t >> 4;            // 0..7  -> rows tr*8 .. tr*8+7
    const int tc = t & 15;            // 0..15 -> cols tc*4 .. tc*4+3
    const int qt = (int)(gridDim.x - 1) - (int)blockIdx.x;  // heavy tiles first
    const int l0 = qt * 64;
    const int bh = blockIdx.y;

    const float* qp = g_q + (size_t)bh * L_ * DH_;
    const float* kp = g_k + (size_t)bh * L_ * DH_;
    const float* vp = g_v + (size_t)bh * L_ * DH_;

    // Load Q tile (8 float4 per thread)
    #pragma unroll
    for (int r = 0; r < 8; r++) {
        int idx = t + r * 128;
        int row = idx >> 4;
        int col = (idx & 15) << 2;
        *(float4*)&Qs[row * 68 + col] =
            *(const float4*)(qp + (size_t)(l0 + row) * DH_ + col);
    }

    const int jb = L_ - 64 - l0;

    // Prologue: first (lo) QE panel, E rows [jb, jb+64)
    #pragma unroll
    for (int r = 0; r < 8; r++) {
        int idx = t + r * 128;
        int row = idx >> 4;
        int col = (idx & 15) << 2;
        *(float4*)&Bs[row * 68 + col] =
            *(const float4*)(E + (size_t)(jb + row) * DH_ + col);
    }
    __syncthreads();
    {
        float qe[8][4] = {};
        dot8x4(&Qs[(tr * 8) * 68], &Bs[(tc * 4) * 68], qe);
        #pragma unroll
        for (int i = 0; i < 8; i++) {
            float4 v = {qe[i][0], qe[i][1], qe[i][2], qe[i][3]};
            *(float4*)&PanA[(tr * 8 + i) * 68 + tc * 4] = v;
        }
    }

    float* plo = PanA;
    float* phi = PanB;

    float Ot[8][4] = {};
    float mrow[8], lrow[8];
    #pragma unroll
    for (int i = 0; i < 8; i++) { mrow[i] = -1e30f; lrow[i] = 0.f; }

    const int ntiles = qt + 1;
    for (int tt = 0; tt < ntiles; tt++) {
        const int m0 = tt * 64;

        // ---- new (hi) QE panel: E rows [jb + 64*(tt+1), +64), clamped ----
        __syncthreads();   // prior readers of Bs done
        #pragma unroll
        for (int r = 0; r < 8; r++) {
            int idx = t + r * 128;
            int row = idx >> 4;
            int col = (idx & 15) << 2;
            int er  = jb + 64 * (tt + 1) + row;
            er = (er < L_) ? er : (L_ - 1);   // OOB rows only feed masked entries
            *(float4*)&Bs[row * 68 + col] =
                *(const float4*)(E + (size_t)er * DH_ + col);
        }
        __syncthreads();
        {
            float qe[8][4] = {};
            dot8x4(&Qs[(tr * 8) * 68], &Bs[(tc * 4) * 68], qe);
            #pragma unroll
            for (int i = 0; i < 8; i++) {
                float4 v = {qe[i][0], qe[i][1], qe[i][2], qe[i][3]};
                *(float4*)&phi[(tr * 8 + i) * 68 + tc * 4] = v;
            }
        }
        __syncthreads();   // panel visible; Bs free

        // ---- K tile + S = Q K^T ----
        #pragma unroll
        for (int r = 0; r < 8; r++) {
            int idx = t + r * 128;
            int row = idx >> 4;
            int col = (idx & 15) << 2;
            *(float4*)&Bs[row * 68 + col] =
                *(const float4*)(kp + (size_t)(m0 + row) * DH_ + col);
        }
        __syncthreads();

        float sacc[8][4] = {};
        dot8x4(&Qs[(tr * 8) * 68], &Bs[(tc * 4) * 68], sacc);

        // gather rel-pos addend, scale, causal mask
        #pragma unroll
        for (int i = 0; i < 8; i++) {
            int li = tr * 8 + i;
            int l  = l0 + li;
            #pragma unroll
            for (int j = 0; j < 4; j++) {
                int mi = tc * 4 + j;
                int c  = 63 - li + mi;
                float rel = (c < 64) ? plo[li * 68 + c] : phi[li * 68 + c - 64];
                float sv  = (sacc[i][j] + rel) * 0.125f;
                sacc[i][j] = (m0 + mi <= l) ? sv : -1e30f;
            }
        }

        __syncthreads();   // K readers done; prev-iter P readers long done

        // ---- V tile load ----
        #pragma unroll
        for (int r = 0; r < 8; r++) {
            int idx = t + r * 128;
            int row = idx >> 4;
            int col = (idx & 15) << 2;
            *(float4*)&Bs[row * 68 + col] =
                *(const float4*)(vp + (size_t)(m0 + row) * DH_ + col);
        }

        // ---- online softmax; P -> Ps ----
        #pragma unroll
        for (int i = 0; i < 8; i++) {
            float mx = fmaxf(fmaxf(sacc[i][0], sacc[i][1]),
                             fmaxf(sacc[i][2], sacc[i][3]));
            #pragma unroll
            for (int off = 8; off > 0; off >>= 1)
                mx = fmaxf(mx, __shfl_xor_sync(0xffffffffu, mx, off));
            float mnew = fmaxf(mrow[i], mx);
            float corr = __expf(mrow[i] - mnew);
            float4 p;
            p.x = __expf(sacc[i][0] - mnew);
            p.y = __expf(sacc[i][1] - mnew);
            p.z = __expf(sacc[i][2] - mnew);
            p.w = __expf(sacc[i][3] - mnew);
            *(float4*)&Ps[(tr * 8 + i) * 68 + tc * 4] = p;
            float psum = p.x + p.y + p.z + p.w;
            #pragma unroll
            for (int off = 8; off > 0; off >>= 1)
                psum += __shfl_xor_sync(0xffffffffu, psum, off);
            lrow[i] = lrow[i] * corr + psum;
            mrow[i] = mnew;
            #pragma unroll
            for (int j = 0; j < 4; j++) Ot[i][j] *= corr;
        }

        __syncthreads();   // V + P visible

        // ---- O += P @ V ----
        #pragma unroll
        for (int kk = 0; kk < 64; kk += 4) {
            float4 p[8], vv[4];
            #pragma unroll
            for (int i = 0; i < 8; i++)
                p[i] = *(const float4*)&Ps[(tr * 8 + i) * 68 + kk];
            #pragma unroll
            for (int u = 0; u < 4; u++)
                vv[u] = *(const float4*)&Bs[(kk + u) * 68 + tc * 4];
            #pragma unroll
            for (int i = 0; i < 8; i++)
                #pragma unroll
                for (int j = 0; j < 4; j++) {
                    float* vj = &((float*)&vv[0])[j];  // not used; explicit below
                    (void)vj;
                    Ot[i][j] = fmaf(p[i].x, ((const float*)&vv[0])[j], Ot[i][j]);
                    Ot[i][j] = fmaf(p[i].y, ((const float*)&vv[1])[j], Ot[i][j]);
                    Ot[i][j] = fmaf(p[i].z, ((const float*)&vv[2])[j], Ot[i][j]);
                    Ot[i][j] = fmaf(p[i].w, ((const float*)&vv[3])[j], Ot[i][j]);
                }
        }

        // swap panels: this iteration's hi becomes next iteration's lo
        float* tmp = plo; plo = phi; phi = tmp;
    }

    float* op = g_o + (size_t)bh * L_ * DH_;
    #pragma unroll
    for (int i = 0; i < 8; i++) {
        float inv = 1.0f / lrow[i];
        int row = l0 + tr * 8 + i;
        float4 o = {Ot[i][0] * inv, Ot[i][1] * inv, Ot[i][2] * inv, Ot[i][3] * inv};
        *(float4*)(op + (size_t)row * DH_ + tc * 4) = o;
    }
}

// ---------------------------------------------------------------------------
extern "C" void kernel_launch(void* const* d_in, const int* in_sizes, int n_in,
                              void* d_out, int out_size)
{
    const float* Q  = (const float*)d_in[0];
    const float* K  = (const float*)d_in[1];
    const float* V  = (const float*)d_in[2];
    // d_in[3] = mask (causal, known analytically) - unused
    const float* Wq = (const float*)d_in[4];
    const float* bq = (const float*)d_in[5];
    const float* Wk = (const float*)d_in[6];
    const float* bk = (const float*)d_in[7];
    const float* Wv = (const float*)d_in[8];
    const float* bv = (const float*)d_in[9];
    const float* Wf = (const float*)d_in[10];
    const float* bf = (const float*)d_in[11];
    const float* E  = (const float*)d_in[12];
    // d_in[13] = H (known constant 8) - unused
    float* out = (float*)d_out;

    (void)in_sizes; (void)n_in; (void)out_size;

    dim3 gproj(NTOK / 128, D_ / 128, 3);
    proj_kernel<<<gproj, 256>>>(Q, K, V, Wq, Wk, Wv, bq, bk, bv);

    const int smem_attn = 5 * 64 * 68 * (int)sizeof(float);  // 87,040 B
    cudaFuncSetAttribute(attn_kernel, cudaFuncAttributeMaxDynamicSharedMemorySize,
                         smem_attn);
    dim3 gattn(L_ / 64, B_ * H_);
    attn_kernel<<<gattn, 128, smem_attn>>>(E);

    dim3 gfc(NTOK / 128, D_ / 128);
    fc_kernel<<<gfc, 256>>>(Wf, bf, out);
}

// round 5
// speedup vs baseline: 6.2246x; 2.7418x over previous
#include <cuda_runtime.h>
#include <cuda_bf16.h>
#include <math.h>
#include <stdint.h>

#define B_  4
#define L_  2048
#define D_  512
#define H_  8
#define DH_ 64
#define NTOK (B_ * L_)   // 8192

// Scratch (allocation-free rule: __device__ globals).
__device__ __nv_bfloat16 g_qh[(size_t)B_ * H_ * L_ * DH_];
__device__ __nv_bfloat16 g_ql[(size_t)B_ * H_ * L_ * DH_];
__device__ __nv_bfloat16 g_kh[(size_t)B_ * H_ * L_ * DH_];
__device__ __nv_bfloat16 g_kl[(size_t)B_ * H_ * L_ * DH_];
__device__ __nv_bfloat16 g_vh[(size_t)B_ * H_ * L_ * DH_];
__device__ __nv_bfloat16 g_vl[(size_t)B_ * H_ * L_ * DH_];
__device__ __nv_bfloat16 g_eh[(size_t)L_ * DH_];
__device__ __nv_bfloat16 g_el[(size_t)L_ * DH_];
__device__ float g_o[(size_t)B_ * H_ * L_ * DH_];

// ===========================================================================
// helpers
// ===========================================================================
__device__ __forceinline__ uint32_t smem_u32(const void* p) {
    uint32_t a;
    asm("{ .reg .u64 t; cvta.to.shared.u64 t, %1; cvt.u32.u64 %0, t; }"
        : "=r"(a) : "l"(p));
    return a;
}

// pack two floats as bf16x2 (x -> low half), plus the residual pair
__device__ __forceinline__ void split2(float x, float y, uint32_t& h, uint32_t& lo) {
    __nv_bfloat162 hh = __floats2bfloat162_rn(x, y);
    float hx = __bfloat162float(hh.x), hy = __bfloat162float(hh.y);
    __nv_bfloat162 ll = __floats2bfloat162_rn(x - hx, y - hy);
    h  = *reinterpret_cast<uint32_t*>(&hh);
    lo = *reinterpret_cast<uint32_t*>(&ll);
}

__device__ __forceinline__ void mma_bf16(float c[4], const uint32_t a[4],
                                         uint32_t b0, uint32_t b1) {
    asm volatile(
        "mma.sync.aligned.m16n8k16.row.col.f32.bf16.bf16.f32 "
        "{%0,%1,%2,%3}, {%4,%5,%6,%7}, {%8,%9}, {%0,%1,%2,%3};"
        : "+f"(c[0]), "+f"(c[1]), "+f"(c[2]), "+f"(c[3])
        : "r"(a[0]), "r"(a[1]), "r"(a[2]), "r"(a[3]), "r"(b0), "r"(b1));
}

__device__ __forceinline__ void ldsm4(uint32_t r[4], uint32_t addr) {
    asm volatile("ldmatrix.sync.aligned.m8n8.x4.shared.b16 {%0,%1,%2,%3}, [%4];"
                 : "=r"(r[0]), "=r"(r[1]), "=r"(r[2]), "=r"(r[3]) : "r"(addr));
}
__device__ __forceinline__ void ldsm4t(uint32_t r[4], uint32_t addr) {
    asm volatile("ldmatrix.sync.aligned.m8n8.x4.trans.shared.b16 {%0,%1,%2,%3}, [%4];"
                 : "=r"(r[0]), "=r"(r[1]), "=r"(r[2]), "=r"(r[3]) : "r"(addr));
}

// ---------------------------------------------------------------------------
// E split prep
// ---------------------------------------------------------------------------
__global__ void eprep_kernel(const float* __restrict__ E) {
    int i = blockIdx.x * 256 + threadIdx.x;
    if (i < L_ * DH_) {
        float x = E[i];
        __nv_bfloat16 h = __float2bfloat16_rn(x);
        g_eh[i] = h;
        g_el[i] = __float2bfloat16_rn(x - __bfloat162float(h));
    }
}

// ---------------------------------------------------------------------------
// QKV projection (SIMT, 128x128 tile, 8x8 reg tile) -> bf16 hi/lo head layout
// ---------------------------------------------------------------------------
__global__ __launch_bounds__(256) void proj_kernel(
    const float* __restrict__ Xq, const float* __restrict__ Xk, const float* __restrict__ Xv,
    const float* __restrict__ Wq, const float* __restrict__ Wk, const float* __restrict__ Wv,
    const float* __restrict__ bq, const float* __restrict__ bk, const float* __restrict__ bv)
{
    __shared__ float As[16][132];
    __shared__ float Ws[16][132];

    const float *X, *W, *bias;
    __nv_bfloat16 *Yh, *Yl;
    if (blockIdx.z == 0)      { X = Xq; W = Wq; bias = bq; Yh = g_qh; Yl = g_ql; }
    else if (blockIdx.z == 1) { X = Xk; W = Wk; bias = bk; Yh = g_kh; Yl = g_kl; }
    else                      { X = Xv; W = Wv; bias = bv; Yh = g_vh; Yl = g_vl; }

    const int t  = threadIdx.x;
    const int tr = t >> 4;
    const int tc = t & 15;
    const int m0 = blockIdx.x * 128;
    const int n0 = blockIdx.y * 128;

    float acc[8][8] = {};

    for (int k0 = 0; k0 < D_; k0 += 16) {
        #pragma unroll
        for (int rep = 0; rep < 2; rep++) {
            int id  = t + rep * 256;
            int row = id >> 2;
            int kg  = (id & 3) << 2;
            float4 xa = *(const float4*)(X + (size_t)(m0 + row) * D_ + k0 + kg);
            float4 wa = *(const float4*)(W + (size_t)(n0 + row) * D_ + k0 + kg);
            As[kg + 0][row] = xa.x; As[kg + 1][row] = xa.y;
            As[kg + 2][row] = xa.z; As[kg + 3][row] = xa.w;
            Ws[kg + 0][row] = wa.x; Ws[kg + 1][row] = wa.y;
            Ws[kg + 2][row] = wa.z; Ws[kg + 3][row] = wa.w;
        }
        __syncthreads();
        #pragma unroll
        for (int kk = 0; kk < 16; kk++) {
            float4 a0 = *(const float4*)&As[kk][tr << 2];
            float4 a1 = *(const float4*)&As[kk][64 + (tr << 2)];
            float4 b0 = *(const float4*)&Ws[kk][tc << 2];
            float4 b1 = *(const float4*)&Ws[kk][64 + (tc << 2)];
            float a[8] = {a0.x, a0.y, a0.z, a0.w, a1.x, a1.y, a1.z, a1.w};
            float b[8] = {b0.x, b0.y, b0.z, b0.w, b1.x, b1.y, b1.z, b1.w};
            #pragma unroll
            for (int i = 0; i < 8; i++)
                #pragma unroll
                for (int j = 0; j < 8; j++)
                    acc[i][j] = fmaf(a[i], b[j], acc[i][j]);
        }
        __syncthreads();
    }

    #pragma unroll
    for (int ih = 0; ih < 2; ih++) {
        #pragma unroll
        for (int i = 0; i < 4; i++) {
            int n  = m0 + ih * 64 + (tr << 2) + i;
            int bb = n >> 11;
            int ll = n & (L_ - 1);
            #pragma unroll
            for (int jh = 0; jh < 2; jh++) {
                int col = n0 + jh * 64 + (tc << 2);
                int hh  = col >> 6;
                int dh  = col & 63;
                float ox = acc[ih * 4 + i][jh * 4 + 0] + bias[col + 0];
                float oy = acc[ih * 4 + i][jh * 4 + 1] + bias[col + 1];
                float oz = acc[ih * 4 + i][jh * 4 + 2] + bias[col + 2];
                float ow = acc[ih * 4 + i][jh * 4 + 3] + bias[col + 3];
                uint32_t h01, l01, h23, l23;
                split2(ox, oy, h01, l01);
                split2(oz, ow, h23, l23);
                size_t off = (((size_t)bb * H_ + hh) * L_ + ll) * DH_ + dh;
                *(uint2*)(Yh + off) = make_uint2(h01, h23);
                *(uint2*)(Yl + off) = make_uint2(l01, l23);
            }
        }
    }
}

// ---------------------------------------------------------------------------
// Output projection (SIMT, unchanged): gathers (B,H,L,DH) fp32 -> out
// ---------------------------------------------------------------------------
__global__ __launch_bounds__(256) void fc_kernel(
    const float* __restrict__ Wf, const float* __restrict__ bf, float* __restrict__ out)
{
    __shared__ float As[16][132];
    __shared__ float Ws[16][132];

    const int t  = threadIdx.x;
    const int tr = t >> 4;
    const int tc = t & 15;
    const int m0 = blockIdx.x * 128;
    const int n0 = blockIdx.y * 128;

    float acc[8][8] = {};

    for (int k0 = 0; k0 < D_; k0 += 16) {
        #pragma unroll
        for (int rep = 0; rep < 2; rep++) {
            int id  = t + rep * 256;
            int row = id >> 2;
            int kg  = (id & 3) << 2;
            int n   = m0 + row;
            int bb  = n >> 11;
            int ll  = n & (L_ - 1);
            int d   = k0 + kg;
            int hh  = d >> 6;
            int dh  = d & 63;
            float4 xa = *(const float4*)(g_o + (((size_t)bb * H_ + hh) * L_ + ll) * DH_ + dh);
            float4 wa = *(const float4*)(Wf + (size_t)(n0 + row) * D_ + k0 + kg);
            As[kg + 0][row] = xa.x; As[kg + 1][row] = xa.y;
            As[kg + 2][row] = xa.z; As[kg + 3][row] = xa.w;
            Ws[kg + 0][row] = wa.x; Ws[kg + 1][row] = wa.y;
            Ws[kg + 2][row] = wa.z; Ws[kg + 3][row] = wa.w;
        }
        __syncthreads();
        #pragma unroll
        for (int kk = 0; kk < 16; kk++) {
            float4 a0 = *(const float4*)&As[kk][tr << 2];
            float4 a1 = *(const float4*)&As[kk][64 + (tr << 2)];
            float4 b0 = *(const float4*)&Ws[kk][tc << 2];
            float4 b1 = *(const float4*)&Ws[kk][64 + (tc << 2)];
            float a[8] = {a0.x, a0.y, a0.z, a0.w, a1.x, a1.y, a1.z, a1.w};
            float b[8] = {b0.x, b0.y, b0.z, b0.w, b1.x, b1.y, b1.z, b1.w};
            #pragma unroll
            for (int i = 0; i < 8; i++)
                #pragma unroll
                for (int j = 0; j < 8; j++)
                    acc[i][j] = fmaf(a[i], b[j], acc[i][j]);
        }
        __syncthreads();
    }

    #pragma unroll
    for (int ih = 0; ih < 2; ih++) {
        #pragma unroll
        for (int i = 0; i < 4; i++) {
            int n = m0 + ih * 64 + (tr << 2) + i;
            #pragma unroll
            for (int jh = 0; jh < 2; jh++) {
                int col = n0 + jh * 64 + (tc << 2);
                float4 o;
                o.x = acc[ih * 4 + i][jh * 4 + 0] + bf[col + 0];
                o.y = acc[ih * 4 + i][jh * 4 + 1] + bf[col + 1];
                o.z = acc[ih * 4 + i][jh * 4 + 2] + bf[col + 2];
                o.w = acc[ih * 4 + i][jh * 4 + 3] + bf[col + 3];
                *(float4*)(out + (size_t)n * D_ + col) = o;
            }
        }
    }
}

// ===========================================================================
// Attention: flash-style causal + rel-pos, mma.sync bf16 split-3.
// 128 threads (4 warps); warp w owns q rows [w*16, w*16+16).
// smem (bytes):
//   PanA fp32 64x68 @ 0      (17408)   [Q hi/lo tiles alias 0..18432 in prologue]
//   PanB fp32 64x68 @ 17408  (17408)
//   WORK hi bf16 64x72 @ 34816 (9216)
//   WORK lo bf16 64x72 @ 44032 (9216)   total 53248
// ===========================================================================
#define PAN_A   0
#define PAN_B   17408
#define QH_OFF  0
#define QL_OFF  9216
#define WORK_H  34816
#define WORK_L  44032
#define ATTN_SMEM 53248
#define TSTRIDE 144   // bytes per smem tile row (72 bf16)

__device__ __forceinline__ void load_tile(char* smc, int woff_h, int woff_l,
    const __nv_bfloat16* __restrict__ sh, const __nv_bfloat16* __restrict__ sl,
    int rowbase, int t, int clampE)
{
    #pragma unroll
    for (int r = 0; r < 4; r++) {
        int idx = t + r * 128;
        int row = idx >> 3, c8 = idx & 7;
        int gr = rowbase + row;
        if (clampE) gr = (gr < L_) ? gr : (L_ - 1);
        *(uint4*)(smc + woff_h + row * TSTRIDE + c8 * 16) =
            *(const uint4*)(sh + (size_t)gr * DH_ + c8 * 8);
        *(uint4*)(smc + woff_l + row * TSTRIDE + c8 * 16) =
            *(const uint4*)(sl + (size_t)gr * DH_ + c8 * 8);
    }
}

// acc[8][4] = Qwarp(16 x 64) * tile(64 x 64)^T, 3-pass split
__device__ __forceinline__ void gemm_tile(float acc[8][4],
    const uint32_t qfh[4][4], const uint32_t qfl[4][4],
    uint32_t th, uint32_t tl, uint32_t boff)
{
    #pragma unroll
    for (int f = 0; f < 8; f++)
        #pragma unroll
        for (int c = 0; c < 4; c++) acc[f][c] = 0.f;
    #pragma unroll
    for (int kc = 0; kc < 4; kc++) {
        #pragma unroll
        for (int nbp = 0; nbp < 4; nbp++) {
            uint32_t a = (uint32_t)(nbp * 16 * TSTRIDE + kc * 32) + boff;
            uint32_t bh_[4], bl_[4];
            ldsm4(bh_, th + a);
            ldsm4(bl_, tl + a);
            mma_bf16(acc[2 * nbp],     qfh[kc], bh_[0], bh_[1]);
            mma_bf16(acc[2 * nbp],     qfh[kc], bl_[0], bl_[1]);
            mma_bf16(acc[2 * nbp],     qfl[kc], bh_[0], bh_[1]);
            mma_bf16(acc[2 * nbp + 1], qfh[kc], bh_[2], bh_[3]);
            mma_bf16(acc[2 * nbp + 1], qfh[kc], bl_[2], bl_[3]);
            mma_bf16(acc[2 * nbp + 1], qfl[kc], bh_[2], bh_[3]);
        }
    }
}

__device__ __forceinline__ void store_panel(float* pan, const float acc[8][4],
                                            int prow, int tq)
{
    #pragma unroll
    for (int f = 0; f < 8; f++) {
        *(float2*)&pan[prow * 68 + 8 * f + 2 * tq]       = make_float2(acc[f][0], acc[f][1]);
        *(float2*)&pan[(prow + 8) * 68 + 8 * f + 2 * tq] = make_float2(acc[f][2], acc[f][3]);
    }
}

__global__ __launch_bounds__(128) void attn_kernel()
{
    extern __shared__ char smc[];
    const uint32_t sbase = smem_u32(smc);
    float* PanAp = (float*)(smc + PAN_A);
    float* PanBp = (float*)(smc + PAN_B);

    const int t  = threadIdx.x;
    const int w  = t >> 5;
    const int ln = t & 31;
    const int g  = ln >> 2;
    const int tq = ln & 3;
    const int qt = (int)(gridDim.x - 1) - (int)blockIdx.x;  // heavy first
    const int l0 = qt * 64;
    const int bh = blockIdx.y;

    const size_t hoff = (size_t)bh * L_ * DH_;

    // lane-constant smem offsets
    const uint32_t aoff = (uint32_t)((w * 16 + (ln & 15)) * TSTRIDE + (ln >> 4) * 16);
    const uint32_t boff = (uint32_t)(((ln & 7) + ((ln >> 4) << 3)) * TSTRIDE + (((ln >> 3) & 1) << 4));
    const uint32_t voff = (uint32_t)(((ln & 7) + (((ln >> 3) & 1) << 3)) * TSTRIDE + ((ln >> 4) << 4));

    // --- prologue: Q tiles into smem (alias panel region), E tile into WORK ---
    #pragma unroll
    for (int r = 0; r < 4; r++) {
        int idx = t + r * 128;
        int row = idx >> 3, c8 = idx & 7;
        *(uint4*)(smc + QH_OFF + row * TSTRIDE + c8 * 16) =
            *(const uint4*)(g_qh + hoff + (size_t)(l0 + row) * DH_ + c8 * 8);
        *(uint4*)(smc + QL_OFF + row * TSTRIDE + c8 * 16) =
            *(const uint4*)(g_ql + hoff + (size_t)(l0 + row) * DH_ + c8 * 8);
    }
    const int jb = L_ - 64 - l0;
    load_tile(smc, WORK_H, WORK_L, g_eh, g_el, jb, t, 0);
    __syncthreads();

    // --- extract Q fragments (persist across all iterations) ---
    uint32_t qfh[4][4], qfl[4][4];
    #pragma unroll
    for (int kc = 0; kc < 4; kc++) {
        ldsm4(qfh[kc], sbase + QH_OFF + kc * 32 + aoff);
        ldsm4(qfl[kc], sbase + QL_OFF + kc * 32 + aoff);
    }
    __syncthreads();   // Q smem dead; panels may now be written

    float acc[8][4];
    // prologue panel -> PanA
    gemm_tile(acc, qfh, qfl, sbase + WORK_H, sbase + WORK_L, boff);
    store_panel(PanAp, acc, w * 16 + g, tq);

    float* plo = PanAp;
    float* phi = PanBp;

    float Oa[8][4] = {};
    float rm0 = -1e30f, rm1 = -1e30f, rl0 = 0.f, rl1 = 0.f;

    const int rt0 = w * 16 + g;
    const int rt1 = rt0 + 8;
    const int ntiles = qt + 1;

    for (int tt = 0; tt < ntiles; tt++) {
        const int m0k = tt * 64;

        __syncthreads();   // prev V reads + old-panel gathers done
        load_tile(smc, WORK_H, WORK_L, g_eh, g_el, jb + 64 * (tt + 1), t, 1);
        __syncthreads();

        gemm_tile(acc, qfh, qfl, sbase + WORK_H, sbase + WORK_L, boff);
        store_panel(phi, acc, rt0, tq);
        __syncthreads();   // panel visible; WORK free

        load_tile(smc, WORK_H, WORK_L, g_kh + hoff, g_kl + hoff, m0k, t, 0);
        __syncthreads();

        gemm_tile(acc, qfh, qfl, sbase + WORK_H, sbase + WORK_L, boff);

        // rel-pos gather + scale + causal mask
        #pragma unroll
        for (int f = 0; f < 8; f++) {
            int mi = 8 * f + 2 * tq;
            #pragma unroll
            for (int c = 0; c < 2; c++) {
                int cc = 63 - rt0 + mi + c;
                float rel = (cc < 64) ? plo[rt0 * 68 + cc] : phi[rt0 * 68 + cc - 64];
                float sv  = (acc[f][c] + rel) * 0.125f;
                acc[f][c] = (m0k + mi + c <= l0 + rt0) ? sv : -1e30f;
            }
            #pragma unroll
            for (int c = 0; c < 2; c++) {
                int cc = 63 - rt1 + mi + c;
                float rel = (cc < 64) ? plo[rt1 * 68 + cc] : phi[rt1 * 68 + cc - 64];
                float sv  = (acc[f][2 + c] + rel) * 0.125f;
                acc[f][2 + c] = (m0k + mi + c <= l0 + rt1) ? sv : -1e30f;
            }
        }
        __syncthreads();   // K reads + panel reads done

        load_tile(smc, WORK_H, WORK_L, g_vh + hoff, g_vl + hoff, m0k, t, 0);

        // --- online softmax (registers + quad shuffles) ---
        float mx0 = -1e30f, mx1 = -1e30f;
        #pragma unroll
        for (int f = 0; f < 8; f++) {
            mx0 = fmaxf(mx0, fmaxf(acc[f][0], acc[f][1]));
            mx1 = fmaxf(mx1, fmaxf(acc[f][2], acc[f][3]));
        }
        mx0 = fmaxf(mx0, __shfl_xor_sync(0xffffffffu, mx0, 1));
        mx0 = fmaxf(mx0, __shfl_xor_sync(0xffffffffu, mx0, 2));
        mx1 = fmaxf(mx1, __shfl_xor_sync(0xffffffffu, mx1, 1));
        mx1 = fmaxf(mx1, __shfl_xor_sync(0xffffffffu, mx1, 2));
        float mn0 = fmaxf(rm0, mx0), mn1 = fmaxf(rm1, mx1);
        float cr0 = __expf(rm0 - mn0), cr1 = __expf(rm1 - mn1);
        float s0 = 0.f, s1 = 0.f;
        #pragma unroll
        for (int f = 0; f < 8; f++) {
            acc[f][0] = __expf(acc[f][0] - mn0); s0 += acc[f][0];
            acc[f][1] = __expf(acc[f][1] - mn0); s0 += acc[f][1];
            acc[f][2] = __expf(acc[f][2] - mn1); s1 += acc[f][2];
            acc[f][3] = __expf(acc[f][3] - mn1); s1 += acc[f][3];
        }
        s0 += __shfl_xor_sync(0xffffffffu, s0, 1);
        s0 += __shfl_xor_sync(0xffffffffu, s0, 2);
        s1 += __shfl_xor_sync(0xffffffffu, s1, 1);
        s1 += __shfl_xor_sync(0xffffffffu, s1, 2);
        rl0 = rl0 * cr0 + s0; rm0 = mn0;
        rl1 = rl1 * cr1 + s1; rm1 = mn1;
        #pragma unroll
        for (int f = 0; f < 8; f++) {
            Oa[f][0] *= cr0; Oa[f][1] *= cr0;
            Oa[f][2] *= cr1; Oa[f][3] *= cr1;
        }
        __syncthreads();   // V visible

        // --- O += P @ V (P converted to A-fragments in registers) ---
        #pragma unroll
        for (int kc = 0; kc < 4; kc++) {
            uint32_t pha[4], pla[4];
            split2(acc[2 * kc][0],     acc[2 * kc][1],     pha[0], pla[0]);
            split2(acc[2 * kc][2],     acc[2 * kc][3],     pha[1], pla[1]);
            split2(acc[2 * kc + 1][0], acc[2 * kc + 1][1], pha[2], pla[2]);
            split2(acc[2 * kc + 1][2], acc[2 * kc + 1][3], pha[3], pla[3]);
            #pragma unroll
            for (int nb = 0; nb < 4; nb++) {
                uint32_t a = (uint32_t)(kc * 16 * TSTRIDE + nb * 32) + voff;
                uint32_t vh_[4], vl_[4];
                ldsm4t(vh_, sbase + WORK_H + a);
                ldsm4t(vl_, sbase + WORK_L + a);
                mma_bf16(Oa[2 * nb],     pha, vh_[0], vh_[1]);
                mma_bf16(Oa[2 * nb],     pha, vl_[0], vl_[1]);
                mma_bf16(Oa[2 * nb],     pla, vh_[0], vh_[1]);
                mma_bf16(Oa[2 * nb + 1], pha, vh_[2], vh_[3]);
                mma_bf16(Oa[2 * nb + 1], pha, vl_[2], vl_[3]);
                mma_bf16(Oa[2 * nb + 1], pla, vh_[2], vh_[3]);
            }
        }

        float* tmp = plo; plo = phi; phi = tmp;
    }

    // --- epilogue ---
    float inv0 = 1.0f / rl0, inv1 = 1.0f / rl1;
    float* op = g_o + hoff;
    #pragma unroll
    for (int f = 0; f < 8; f++) {
        int col = 8 * f + 2 * tq;
        *(float2*)(op + (size_t)(l0 + rt0) * DH_ + col) =
            make_float2(Oa[f][0] * inv0, Oa[f][1] * inv0);
        *(float2*)(op + (size_t)(l0 + rt1) * DH_ + col) =
            make_float2(Oa[f][2] * inv1, Oa[f][3] * inv1);
    }
}

// ---------------------------------------------------------------------------
extern "C" void kernel_launch(void* const* d_in, const int* in_sizes, int n_in,
                              void* d_out, int out_size)
{
    const float* Q  = (const float*)d_in[0];
    const float* K  = (const float*)d_in[1];
    const float* V  = (const float*)d_in[2];
    // d_in[3] = mask (causal, known analytically) - unused
    const float* Wq = (const float*)d_in[4];
    const float* bq = (const float*)d_in[5];
    const float* Wk = (const float*)d_in[6];
    const float* bk = (const float*)d_in[7];
    const float* Wv = (const float*)d_in[8];
    const float* bv = (const float*)d_in[9];
    const float* Wf = (const float*)d_in[10];
    const float* bf = (const float*)d_in[11];
    const float* E  = (const float*)d_in[12];
    // d_in[13] = H (known constant 8) - unused
    float* out = (float*)d_out;

    (void)in_sizes; (void)n_in; (void)out_size;

    eprep_kernel<<<(L_ * DH_ + 255) / 256, 256>>>(E);

    dim3 gproj(NTOK / 128, D_ / 128, 3);
    proj_kernel<<<gproj, 256>>>(Q, K, V, Wq, Wk, Wv, bq, bk, bv);

    cudaFuncSetAttribute(attn_kernel, cudaFuncAttributeMaxDynamicSharedMemorySize,
                         ATTN_SMEM);
    dim3 gattn(L_ / 64, B_ * H_);
    attn_kernel<<<gattn, 128, ATTN_SMEM>>>();

    dim3 gfc(NTOK / 128, D_ / 128);
    fc_kernel<<<gfc, 256>>>(Wf, bf, out);
}

// round 6
// speedup vs baseline: 8.7141x; 1.4000x over previous
#include <cuda_runtime.h>
#include <cuda_bf16.h>
#include <math.h>
#include <stdint.h>

#define B_  4
#define L_  2048
#define D_  512
#define H_  8
#define DH_ 64
#define NTOK (B_ * L_)   // 8192

// Scratch (allocation-free rule: __device__ globals).
__device__ __nv_bfloat16 g_qh[(size_t)B_ * H_ * L_ * DH_];
__device__ __nv_bfloat16 g_ql[(size_t)B_ * H_ * L_ * DH_];
__device__ __nv_bfloat16 g_kh[(size_t)B_ * H_ * L_ * DH_];
__device__ __nv_bfloat16 g_kl[(size_t)B_ * H_ * L_ * DH_];
__device__ __nv_bfloat16 g_vh[(size_t)B_ * H_ * L_ * DH_];
__device__ __nv_bfloat16 g_vl[(size_t)B_ * H_ * L_ * DH_];
__device__ __nv_bfloat16 g_eh[(size_t)L_ * DH_];
__device__ __nv_bfloat16 g_el[(size_t)L_ * DH_];
__device__ float g_o[(size_t)B_ * H_ * L_ * DH_];

// ===========================================================================
// helpers
// ===========================================================================
__device__ __forceinline__ uint32_t smem_u32(const void* p) {
    uint32_t a;
    asm("{ .reg .u64 t; cvta.to.shared.u64 t, %1; cvt.u32.u64 %0, t; }"
        : "=r"(a) : "l"(p));
    return a;
}

// pack two floats as bf16x2 (x -> low half), plus the residual pair
__device__ __forceinline__ void split2(float x, float y, uint32_t& h, uint32_t& lo) {
    __nv_bfloat162 hh = __floats2bfloat162_rn(x, y);
    float hx = __bfloat162float(hh.x), hy = __bfloat162float(hh.y);
    __nv_bfloat162 ll = __floats2bfloat162_rn(x - hx, y - hy);
    h  = *reinterpret_cast<uint32_t*>(&hh);
    lo = *reinterpret_cast<uint32_t*>(&ll);
}

__device__ __forceinline__ void mma_bf16(float c[4], const uint32_t a[4],
                                         uint32_t b0, uint32_t b1) {
    asm volatile(
        "mma.sync.aligned.m16n8k16.row.col.f32.bf16.bf16.f32 "
        "{%0,%1,%2,%3}, {%4,%5,%6,%7}, {%8,%9}, {%0,%1,%2,%3};"
        : "+f"(c[0]), "+f"(c[1]), "+f"(c[2]), "+f"(c[3])
        : "r"(a[0]), "r"(a[1]), "r"(a[2]), "r"(a[3]), "r"(b0), "r"(b1));
}

__device__ __forceinline__ void ldsm4(uint32_t r[4], uint32_t addr) {
    asm volatile("ldmatrix.sync.aligned.m8n8.x4.shared.b16 {%0,%1,%2,%3}, [%4];"
                 : "=r"(r[0]), "=r"(r[1]), "=r"(r[2]), "=r"(r[3]) : "r"(addr));
}
__device__ __forceinline__ void ldsm4t(uint32_t r[4], uint32_t addr) {
    asm volatile("ldmatrix.sync.aligned.m8n8.x4.trans.shared.b16 {%0,%1,%2,%3}, [%4];"
                 : "=r"(r[0]), "=r"(r[1]), "=r"(r[2]), "=r"(r[3]) : "r"(addr));
}

// ---------------------------------------------------------------------------
// E split prep
// ---------------------------------------------------------------------------
__global__ void eprep_kernel(const float* __restrict__ E) {
    int i = blockIdx.x * 256 + threadIdx.x;
    if (i < L_ * DH_) {
        float x = E[i];
        __nv_bfloat16 h = __float2bfloat16_rn(x);
        g_eh[i] = h;
        g_el[i] = __float2bfloat16_rn(x - __bfloat162float(h));
    }
}

// ===========================================================================
// MMA GEMM common machinery (128x128 CTA tile, 256 threads, 8 warps 4x2,
// warp tile 32x64, K chunk 32, 2-stage smem double buffer).
// smem stage layout (bytes): Ah @0, Al @10240, Bh @20480, Bl @30720
// row stride 80 B (32 bf16 + 8 pad). Stage size 40960, total 81920.
// ===========================================================================
#define GSTRIDE 80
#define PANEL   10240
#define STAGE   40960
#define GEMM_SMEM (2 * STAGE)
#define KCH 16

__device__ __forceinline__ void cvt_sts(char* smc, uint32_t off, float4 v) {
    uint32_t h01, l01, h23, l23;
    split2(v.x, v.y, h01, l01);
    split2(v.z, v.w, h23, l23);
    *(uint2*)(smc + off)         = make_uint2(h01, h23);
    *(uint2*)(smc + off + PANEL) = make_uint2(l01, l23);
}

// one 32-K chunk of 3-pass split MMAs for this warp
__device__ __forceinline__ void gemm_chunk(uint32_t stg, int warp_m, int warp_n,
                                           int ln, float acc[2][8][4])
{
    const uint32_t aoff = (uint32_t)((ln & 15) * GSTRIDE + (ln >> 4) * 16);
    const uint32_t boff = (uint32_t)(((ln & 7) + ((ln >> 4) << 3)) * GSTRIDE
                                     + (((ln >> 3) & 1) << 4));
    #pragma unroll
    for (int ks = 0; ks < 2; ks++) {
        uint32_t ah[2][4], al[2][4];
        #pragma unroll
        for (int mb = 0; mb < 2; mb++) {
            uint32_t base = stg + (uint32_t)((warp_m * 32 + mb * 16) * GSTRIDE + ks * 32) + aoff;
            ldsm4(ah[mb], base);
            ldsm4(al[mb], base + PANEL);
        }
        #pragma unroll
        for (int nb = 0; nb < 4; nb++) {
            uint32_t base = stg + 2 * PANEL
                          + (uint32_t)((warp_n * 64 + nb * 16) * GSTRIDE + ks * 32) + boff;
            uint32_t bh_[4], bl_[4];
            ldsm4(bh_, base);
            ldsm4(bl_, base + PANEL);
            #pragma unroll
            for (int mb = 0; mb < 2; mb++) {
                mma_bf16(acc[mb][2 * nb],     ah[mb], bh_[0], bh_[1]);
                mma_bf16(acc[mb][2 * nb],     ah[mb], bl_[0], bl_[1]);
                mma_bf16(acc[mb][2 * nb],     al[mb], bh_[0], bh_[1]);
                mma_bf16(acc[mb][2 * nb + 1], ah[mb], bh_[2], bh_[3]);
                mma_bf16(acc[mb][2 * nb + 1], ah[mb], bl_[2], bl_[3]);
                mma_bf16(acc[mb][2 * nb + 1], al[mb], bh_[2], bh_[3]);
            }
        }
    }
}

// ---------------------------------------------------------------------------
// QKV projection on tensor cores -> bf16 hi/lo head layout.
// ---------------------------------------------------------------------------
__global__ __launch_bounds__(256) void proj_mma_kernel(
    const float* __restrict__ Xq, const float* __restrict__ Xk, const float* __restrict__ Xv,
    const float* __restrict__ Wq, const float* __restrict__ Wk, const float* __restrict__ Wv,
    const float* __restrict__ bq, const float* __restrict__ bk, const float* __restrict__ bv)
{
    extern __shared__ char smc[];
    const uint32_t sbase = smem_u32(smc);

    const float *X, *W, *bias;
    __nv_bfloat16 *Yh, *Yl;
    if (blockIdx.z == 0)      { X = Xq; W = Wq; bias = bq; Yh = g_qh; Yl = g_ql; }
    else if (blockIdx.z == 1) { X = Xk; W = Wk; bias = bk; Yh = g_kh; Yl = g_kl; }
    else                      { X = Xv; W = Wv; bias = bv; Yh = g_vh; Yl = g_vl; }

    const int t   = threadIdx.x;
    const int wid = t >> 5;
    const int ln  = t & 31;
    const int warp_m = wid >> 1;
    const int warp_n = wid & 1;
    const int m0 = blockIdx.x * 128;
    const int n0 = blockIdx.y * 128;

    // loader indices (per r: one float4 of A and one of B)
    int lrow[4], lcg[4];
    #pragma unroll
    for (int r = 0; r < 4; r++) {
        int idx = t + r * 256;
        lrow[r] = idx >> 3;
        lcg[r]  = idx & 7;
    }

    float acc[2][8][4] = {};
    float4 ra[4], rb[4];

    // preload chunk 0
    #pragma unroll
    for (int r = 0; r < 4; r++) {
        ra[r] = *(const float4*)(X + (size_t)(m0 + lrow[r]) * D_ + lcg[r] * 4);
        rb[r] = *(const float4*)(W + (size_t)(n0 + lrow[r]) * D_ + lcg[r] * 4);
    }
    #pragma unroll
    for (int r = 0; r < 4; r++) {
        uint32_t o = (uint32_t)(lrow[r] * GSTRIDE + lcg[r] * 8);
        cvt_sts(smc, o, ra[r]);
        cvt_sts(smc, 2 * PANEL + o, rb[r]);
    }
    __syncthreads();

    for (int p = 0; p < KCH; p++) {
        const int s = p & 1;
        if (p < KCH - 1) {
            const int k0 = (p + 1) * 32;
            #pragma unroll
            for (int r = 0; r < 4; r++) {
                ra[r] = *(const float4*)(X + (size_t)(m0 + lrow[r]) * D_ + k0 + lcg[r] * 4);
                rb[r] = *(const float4*)(W + (size_t)(n0 + lrow[r]) * D_ + k0 + lcg[r] * 4);
            }
        }
        gemm_chunk(sbase + (uint32_t)s * STAGE, warp_m, warp_n, ln, acc);
        if (p < KCH - 1) {
            const uint32_t so = (uint32_t)(s ^ 1) * STAGE;
            #pragma unroll
            for (int r = 0; r < 4; r++) {
                uint32_t o = so + (uint32_t)(lrow[r] * GSTRIDE + lcg[r] * 8);
                cvt_sts(smc, o, ra[r]);
                cvt_sts(smc, 2 * PANEL + o, rb[r]);
            }
        }
        __syncthreads();
    }

    // epilogue: bias add + bf16 hi/lo split into head layout
    const int g  = ln >> 2;
    const int tq = ln & 3;
    #pragma unroll
    for (int mb = 0; mb < 2; mb++) {
        int r0 = m0 + warp_m * 32 + mb * 16 + g;
        int r1 = r0 + 8;
        int bb0 = r0 >> 11, ll0 = r0 & (L_ - 1);
        int bb1 = r1 >> 11, ll1 = r1 & (L_ - 1);
        #pragma unroll
        for (int f = 0; f < 8; f++) {
            int col = n0 + warp_n * 64 + f * 8 + 2 * tq;
            int hh = col >> 6, dh = col & 63;
            float b0 = bias[col], b1 = bias[col + 1];
            uint32_t h, l;
            size_t o0 = (((size_t)bb0 * H_ + hh) * L_ + ll0) * DH_ + dh;
            split2(acc[mb][f][0] + b0, acc[mb][f][1] + b1, h, l);
            *(uint32_t*)(Yh + o0) = h;
            *(uint32_t*)(Yl + o0) = l;
            size_t o1 = (((size_t)bb1 * H_ + hh) * L_ + ll1) * DH_ + dh;
            split2(acc[mb][f][2] + b0, acc[mb][f][3] + b1, h, l);
            *(uint32_t*)(Yh + o1) = h;
            *(uint32_t*)(Yl + o1) = l;
        }
    }
}

// ---------------------------------------------------------------------------
// Output projection on tensor cores: gathers fp32 (B,H,L,DH) rows -> out.
// ---------------------------------------------------------------------------
__global__ __launch_bounds__(256) void fc_mma_kernel(
    const float* __restrict__ Wf, const float* __restrict__ bf, float* __restrict__ out)
{
    extern __shared__ char smc[];
    const uint32_t sbase = smem_u32(smc);

    const int t   = threadIdx.x;
    const int wid = t >> 5;
    const int ln  = t & 31;
    const int warp_m = wid >> 1;
    const int warp_n = wid & 1;
    const int m0 = blockIdx.x * 128;
    const int n0 = blockIdx.y * 128;

    int lrow[4], lcg[4], lbb[4], lll[4];
    #pragma unroll
    for (int r = 0; r < 4; r++) {
        int idx = t + r * 256;
        lrow[r] = idx >> 3;
        lcg[r]  = idx & 7;
        int n = m0 + lrow[r];
        lbb[r] = n >> 11;
        lll[r] = n & (L_ - 1);
    }

    float acc[2][8][4] = {};
    float4 ra[4], rb[4];

    auto loadA = [&](int r, int k0) -> float4 {
        int d  = k0 + lcg[r] * 4;
        int hh = d >> 6, dh = d & 63;
        return *(const float4*)(g_o + (((size_t)lbb[r] * H_ + hh) * L_ + lll[r]) * DH_ + dh);
    };

    #pragma unroll
    for (int r = 0; r < 4; r++) {
        ra[r] = loadA(r, 0);
        rb[r] = *(const float4*)(Wf + (size_t)(n0 + lrow[r]) * D_ + lcg[r] * 4);
    }
    #pragma unroll
    for (int r = 0; r < 4; r++) {
        uint32_t o = (uint32_t)(lrow[r] * GSTRIDE + lcg[r] * 8);
        cvt_sts(smc, o, ra[r]);
        cvt_sts(smc, 2 * PANEL + o, rb[r]);
    }
    __syncthreads();

    for (int p = 0; p < KCH; p++) {
        const int s = p & 1;
        if (p < KCH - 1) {
            const int k0 = (p + 1) * 32;
            #pragma unroll
            for (int r = 0; r < 4; r++) {
                ra[r] = loadA(r, k0);
                rb[r] = *(const float4*)(Wf + (size_t)(n0 + lrow[r]) * D_ + k0 + lcg[r] * 4);
            }
        }
        gemm_chunk(sbase + (uint32_t)s * STAGE, warp_m, warp_n, ln, acc);
        if (p < KCH - 1) {
            const uint32_t so = (uint32_t)(s ^ 1) * STAGE;
            #pragma unroll
            for (int r = 0; r < 4; r++) {
                uint32_t o = so + (uint32_t)(lrow[r] * GSTRIDE + lcg[r] * 8);
                cvt_sts(smc, o, ra[r]);
                cvt_sts(smc, 2 * PANEL + o, rb[r]);
            }
        }
        __syncthreads();
    }

    const int g  = ln >> 2;
    const int tq = ln & 3;
    #pragma unroll
    for (int mb = 0; mb < 2; mb++) {
        int r0 = m0 + warp_m * 32 + mb * 16 + g;
        int r1 = r0 + 8;
        #pragma unroll
        for (int f = 0; f < 8; f++) {
            int col = n0 + warp_n * 64 + f * 8 + 2 * tq;
            float b0 = bf[col], b1 = bf[col + 1];
            *(float2*)(out + (size_t)r0 * D_ + col) =
                make_float2(acc[mb][f][0] + b0, acc[mb][f][1] + b1);
            *(float2*)(out + (size_t)r1 * D_ + col) =
                make_float2(acc[mb][f][2] + b0, acc[mb][f][3] + b1);
        }
    }
}

// ===========================================================================
// Attention: flash-style causal + rel-pos, mma.sync bf16 split-3 (R5, passing).
// ===========================================================================
#define PAN_A   0
#define PAN_B   17408
#define QH_OFF  0
#define QL_OFF  9216
#define WORK_H  34816
#define WORK_L  44032
#define ATTN_SMEM 53248
#define TSTRIDE 144   // bytes per smem tile row (72 bf16)

__device__ __forceinline__ void load_tile(char* smc, int woff_h, int woff_l,
    const __nv_bfloat16* __restrict__ sh, const __nv_bfloat16* __restrict__ sl,
    int rowbase, int t, int clampE)
{
    #pragma unroll
    for (int r = 0; r < 4; r++) {
        int idx = t + r * 128;
        int row = idx >> 3, c8 = idx & 7;
        int gr = rowbase + row;
        if (clampE) gr = (gr < L_) ? gr : (L_ - 1);
        *(uint4*)(smc + woff_h + row * TSTRIDE + c8 * 16) =
            *(const uint4*)(sh + (size_t)gr * DH_ + c8 * 8);
        *(uint4*)(smc + woff_l + row * TSTRIDE + c8 * 16) =
            *(const uint4*)(sl + (size_t)gr * DH_ + c8 * 8);
    }
}

__device__ __forceinline__ void gemm_tile(float acc[8][4],
    const uint32_t qfh[4][4], const uint32_t qfl[4][4],
    uint32_t th, uint32_t tl, uint32_t boff)
{
    #pragma unroll
    for (int f = 0; f < 8; f++)
        #pragma unroll
        for (int c = 0; c < 4; c++) acc[f][c] = 0.f;
    #pragma unroll
    for (int kc = 0; kc < 4; kc++) {
        #pragma unroll
        for (int nbp = 0; nbp < 4; nbp++) {
            uint32_t a = (uint32_t)(nbp * 16 * TSTRIDE + kc * 32) + boff;
            uint32_t bh_[4], bl_[4];
            ldsm4(bh_, th + a);
            ldsm4(bl_, tl + a);
            mma_bf16(acc[2 * nbp],     qfh[kc], bh_[0], bh_[1]);
            mma_bf16(acc[2 * nbp],     qfh[kc], bl_[0], bl_[1]);
            mma_bf16(acc[2 * nbp],     qfl[kc], bh_[0], bh_[1]);
            mma_bf16(acc[2 * nbp + 1], qfh[kc], bh_[2], bh_[3]);
            mma_bf16(acc[2 * nbp + 1], qfh[kc], bl_[2], bl_[3]);
            mma_bf16(acc[2 * nbp + 1], qfl[kc], bh_[2], bh_[3]);
        }
    }
}

__device__ __forceinline__ void store_panel(float* pan, const float acc[8][4],
                                            int prow, int tq)
{
    #pragma unroll
    for (int f = 0; f < 8; f++) {
        *(float2*)&pan[prow * 68 + 8 * f + 2 * tq]       = make_float2(acc[f][0], acc[f][1]);
        *(float2*)&pan[(prow + 8) * 68 + 8 * f + 2 * tq] = make_float2(acc[f][2], acc[f][3]);
    }
}

__global__ __launch_bounds__(128) void attn_kernel()
{
    extern __shared__ char smc[];
    const uint32_t sbase = smem_u32(smc);
    float* PanAp = (float*)(smc + PAN_A);
    float* PanBp = (float*)(smc + PAN_B);

    const int t  = threadIdx.x;
    const int w  = t >> 5;
    const int ln = t & 31;
    const int g  = ln >> 2;
    const int tq = ln & 3;
    const int qt = (int)(gridDim.x - 1) - (int)blockIdx.x;  // heavy first
    const int l0 = qt * 64;
    const int bh = blockIdx.y;

    const size_t hoff = (size_t)bh * L_ * DH_;

    const uint32_t aoff = (uint32_t)((w * 16 + (ln & 15)) * TSTRIDE + (ln >> 4) * 16);
    const uint32_t boff = (uint32_t)(((ln & 7) + ((ln >> 4) << 3)) * TSTRIDE + (((ln >> 3) & 1) << 4));
    const uint32_t voff = (uint32_t)(((ln & 7) + (((ln >> 3) & 1) << 3)) * TSTRIDE + ((ln >> 4) << 4));

    #pragma unroll
    for (int r = 0; r < 4; r++) {
        int idx = t + r * 128;
        int row = idx >> 3, c8 = idx & 7;
        *(uint4*)(smc + QH_OFF + row * TSTRIDE + c8 * 16) =
            *(const uint4*)(g_qh + hoff + (size_t)(l0 + row) * DH_ + c8 * 8);
        *(uint4*)(smc + QL_OFF + row * TSTRIDE + c8 * 16) =
            *(const uint4*)(g_ql + hoff + (size_t)(l0 + row) * DH_ + c8 * 8);
    }
    const int jb = L_ - 64 - l0;
    load_tile(smc, WORK_H, WORK_L, g_eh, g_el, jb, t, 0);
    __syncthreads();

    uint32_t qfh[4][4], qfl[4][4];
    #pragma unroll
    for (int kc = 0; kc < 4; kc++) {
        ldsm4(qfh[kc], sbase + QH_OFF + kc * 32 + aoff);
        ldsm4(qfl[kc], sbase + QL_OFF + kc * 32 + aoff);
    }
    __syncthreads();

    float acc[8][4];
    gemm_tile(acc, qfh, qfl, sbase + WORK_H, sbase + WORK_L, boff);
    store_panel(PanAp, acc, w * 16 + g, tq);

    float* plo = PanAp;
    float* phi = PanBp;

    float Oa[8][4] = {};
    float rm0 = -1e30f, rm1 = -1e30f, rl0 = 0.f, rl1 = 0.f;

    const int rt0 = w * 16 + g;
    const int rt1 = rt0 + 8;
    const int ntiles = qt + 1;

    for (int tt = 0; tt < ntiles; tt++) {
        const int m0k = tt * 64;

        __syncthreads();
        load_tile(smc, WORK_H, WORK_L, g_eh, g_el, jb + 64 * (tt + 1), t, 1);
        __syncthreads();

        gemm_tile(acc, qfh, qfl, sbase + WORK_H, sbase + WORK_L, boff);
        store_panel(phi, acc, rt0, tq);
        __syncthreads();

        load_tile(smc, WORK_H, WORK_L, g_kh + hoff, g_kl + hoff, m0k, t, 0);
        __syncthreads();

        gemm_tile(acc, qfh, qfl, sbase + WORK_H, sbase + WORK_L, boff);

        #pragma unroll
        for (int f = 0; f < 8; f++) {
            int mi = 8 * f + 2 * tq;
            #pragma unroll
            for (int c = 0; c < 2; c++) {
                int cc = 63 - rt0 + mi + c;
                float rel = (cc < 64) ? plo[rt0 * 68 + cc] : phi[rt0 * 68 + cc - 64];
                float sv  = (acc[f][c] + rel) * 0.125f;
                acc[f][c] = (m0k + mi + c <= l0 + rt0) ? sv : -1e30f;
            }
            #pragma unroll
            for (int c = 0; c < 2; c++) {
                int cc = 63 - rt1 + mi + c;
                float rel = (cc < 64) ? plo[rt1 * 68 + cc] : phi[rt1 * 68 + cc - 64];
                float sv  = (acc[f][2 + c] + rel) * 0.125f;
                acc[f][2 + c] = (m0k + mi + c <= l0 + rt1) ? sv : -1e30f;
            }
        }
        __syncthreads();

        load_tile(smc, WORK_H, WORK_L, g_vh + hoff, g_vl + hoff, m0k, t, 0);

        float mx0 = -1e30f, mx1 = -1e30f;
        #pragma unroll
        for (int f = 0; f < 8; f++) {
            mx0 = fmaxf(mx0, fmaxf(acc[f][0], acc[f][1]));
            mx1 = fmaxf(mx1, fmaxf(acc[f][2], acc[f][3]));
        }
        mx0 = fmaxf(mx0, __shfl_xor_sync(0xffffffffu, mx0, 1));
        mx0 = fmaxf(mx0, __shfl_xor_sync(0xffffffffu, mx0, 2));
        mx1 = fmaxf(mx1, __shfl_xor_sync(0xffffffffu, mx1, 1));
        mx1 = fmaxf(mx1, __shfl_xor_sync(0xffffffffu, mx1, 2));
        float mn0 = fmaxf(rm0, mx0), mn1 = fmaxf(rm1, mx1);
        float cr0 = __expf(rm0 - mn0), cr1 = __expf(rm1 - mn1);
        float s0 = 0.f, s1 = 0.f;
        #pragma unroll
        for (int f = 0; f < 8; f++) {
            acc[f][0] = __expf(acc[f][0] - mn0); s0 += acc[f][0];
            acc[f][1] = __expf(acc[f][1] - mn0); s0 += acc[f][1];
            acc[f][2] = __expf(acc[f][2] - mn1); s1 += acc[f][2];
            acc[f][3] = __expf(acc[f][3] - mn1); s1 += acc[f][3];
        }
        s0 += __shfl_xor_sync(0xffffffffu, s0, 1);
        s0 += __shfl_xor_sync(0xffffffffu, s0, 2);
        s1 += __shfl_xor_sync(0xffffffffu, s1, 1);
        s1 += __shfl_xor_sync(0xffffffffu, s1, 2);
        rl0 = rl0 * cr0 + s0; rm0 = mn0;
        rl1 = rl1 * cr1 + s1; rm1 = mn1;
        #pragma unroll
        for (int f = 0; f < 8; f++) {
            Oa[f][0] *= cr0; Oa[f][1] *= cr0;
            Oa[f][2] *= cr1; Oa[f][3] *= cr1;
        }
        __syncthreads();

        #pragma unroll
        for (int kc = 0; kc < 4; kc++) {
            uint32_t pha[4], pla[4];
            split2(acc[2 * kc][0],     acc[2 * kc][1],     pha[0], pla[0]);
            split2(acc[2 * kc][2],     acc[2 * kc][3],     pha[1], pla[1]);
            split2(acc[2 * kc + 1][0], acc[2 * kc + 1][1], pha[2], pla[2]);
            split2(acc[2 * kc + 1][2], acc[2 * kc + 1][3], pha[3], pla[3]);
            #pragma unroll
            for (int nb = 0; nb < 4; nb++) {
                uint32_t a = (uint32_t)(kc * 16 * TSTRIDE + nb * 32) + voff;
                uint32_t vh_[4], vl_[4];
                ldsm4t(vh_, sbase + WORK_H + a);
                ldsm4t(vl_, sbase + WORK_L + a);
                mma_bf16(Oa[2 * nb],     pha, vh_[0], vh_[1]);
                mma_bf16(Oa[2 * nb],     pha, vl_[0], vl_[1]);
                mma_bf16(Oa[2 * nb],     pla, vh_[0], vh_[1]);
                mma_bf16(Oa[2 * nb + 1], pha, vh_[2], vh_[3]);
                mma_bf16(Oa[2 * nb + 1], pha, vl_[2], vl_[3]);
                mma_bf16(Oa[2 * nb + 1], pla, vh_[2], vh_[3]);
            }
        }

        float* tmp = plo; plo = phi; phi = tmp;
    }

    float inv0 = 1.0f / rl0, inv1 = 1.0f / rl1;
    float* op = g_o + hoff;
    #pragma unroll
    for (int f = 0; f < 8; f++) {
        int col = 8 * f + 2 * tq;
        *(float2*)(op + (size_t)(l0 + rt0) * DH_ + col) =
            make_float2(Oa[f][0] * inv0, Oa[f][1] * inv0);
        *(float2*)(op + (size_t)(l0 + rt1) * DH_ + col) =
            make_float2(Oa[f][2] * inv1, Oa[f][3] * inv1);
    }
}

// ---------------------------------------------------------------------------
extern "C" void kernel_launch(void* const* d_in, const int* in_sizes, int n_in,
                              void* d_out, int out_size)
{
    const float* Q  = (const float*)d_in[0];
    const float* K  = (const float*)d_in[1];
    const float* V  = (const float*)d_in[2];
    // d_in[3] = mask (causal, known analytically) - unused
    const float* Wq = (const float*)d_in[4];
    const float* bq = (const float*)d_in[5];
    const float* Wk = (const float*)d_in[6];
    const float* bk = (const float*)d_in[7];
    const float* Wv = (const float*)d_in[8];
    const float* bv = (const float*)d_in[9];
    const float* Wf = (const float*)d_in[10];
    const float* bf = (const float*)d_in[11];
    const float* E  = (const float*)d_in[12];
    // d_in[13] = H (known constant 8) - unused
    float* out = (float*)d_out;

    (void)in_sizes; (void)n_in; (void)out_size;

    eprep_kernel<<<(L_ * DH_ + 255) / 256, 256>>>(E);

    cudaFuncSetAttribute(proj_mma_kernel, cudaFuncAttributeMaxDynamicSharedMemorySize,
                         GEMM_SMEM);
    cudaFuncSetAttribute(fc_mma_kernel, cudaFuncAttributeMaxDynamicSharedMemorySize,
                         GEMM_SMEM);
    cudaFuncSetAttribute(attn_kernel, cudaFuncAttributeMaxDynamicSharedMemorySize,
                         ATTN_SMEM);

    dim3 gproj(NTOK / 128, D_ / 128, 3);
    proj_mma_kernel<<<gproj, 256, GEMM_SMEM>>>(Q, K, V, Wq, Wk, Wv, bq, bk, bv);

    dim3 gattn(L_ / 64, B_ * H_);
    attn_kernel<<<gattn, 128, ATTN_SMEM>>>();

    dim3 gfc(NTOK / 128, D_ / 128);
    fc_mma_kernel<<<gfc, 256, GEMM_SMEM>>>(Wf, bf, out);
}

// round 7
// speedup vs baseline: 15.8749x; 1.8217x over previous
#include <cuda_runtime.h>
#include <cuda_fp16.h>
#include <math.h>
#include <stdint.h>

#define B_  4
#define L_  2048
#define D_  512
#define H_  8
#define DH_ 64
#define NTOK (B_ * L_)   // 8192

// Scratch (allocation-free rule: __device__ globals). All fp16 single-precision-split-free.
__device__ __half g_q[(size_t)B_ * H_ * L_ * DH_];
__device__ __half g_k[(size_t)B_ * H_ * L_ * DH_];
__device__ __half g_v[(size_t)B_ * H_ * L_ * DH_];
__device__ __half g_e[(size_t)L_ * DH_];
__device__ __half g_oh[(size_t)B_ * H_ * L_ * DH_];

// ===========================================================================
// helpers
// ===========================================================================
__device__ __forceinline__ uint32_t smem_u32(const void* p) {
    uint32_t a;
    asm("{ .reg .u64 t; cvta.to.shared.u64 t, %1; cvt.u32.u64 %0, t; }"
        : "=r"(a) : "l"(p));
    return a;
}

__device__ __forceinline__ uint32_t pack2h(float x, float y) {
    __half2 h = __floats2half2_rn(x, y);
    return *reinterpret_cast<uint32_t*>(&h);
}

__device__ __forceinline__ float fex2(float x) {
    float r;
    asm("ex2.approx.f32 %0, %1;" : "=f"(r) : "f"(x));
    return r;
}

__device__ __forceinline__ void mma_f16(float c[4], const uint32_t a[4],
                                        uint32_t b0, uint32_t b1) {
    asm volatile(
        "mma.sync.aligned.m16n8k16.row.col.f32.f16.f16.f32 "
        "{%0,%1,%2,%3}, {%4,%5,%6,%7}, {%8,%9}, {%0,%1,%2,%3};"
        : "+f"(c[0]), "+f"(c[1]), "+f"(c[2]), "+f"(c[3])
        : "r"(a[0]), "r"(a[1]), "r"(a[2]), "r"(a[3]), "r"(b0), "r"(b1));
}

__device__ __forceinline__ void ldsm4(uint32_t r[4], uint32_t addr) {
    asm volatile("ldmatrix.sync.aligned.m8n8.x4.shared.b16 {%0,%1,%2,%3}, [%4];"
                 : "=r"(r[0]), "=r"(r[1]), "=r"(r[2]), "=r"(r[3]) : "r"(addr));
}
__device__ __forceinline__ void ldsm4t(uint32_t r[4], uint32_t addr) {
    asm volatile("ldmatrix.sync.aligned.m8n8.x4.trans.shared.b16 {%0,%1,%2,%3}, [%4];"
                 : "=r"(r[0]), "=r"(r[1]), "=r"(r[2]), "=r"(r[3]) : "r"(addr));
}

// ---------------------------------------------------------------------------
// E fp16 prep
// ---------------------------------------------------------------------------
__global__ void eprep_kernel(const float* __restrict__ E) {
    int i = blockIdx.x * 256 + threadIdx.x;
    if (i < L_ * DH_) g_e[i] = __float2half_rn(E[i]);
}

// ===========================================================================
// MMA GEMM machinery (128x128 CTA tile, 256 threads, 8 warps 4x2,
// warp tile 32x64, K chunk 32, 2-stage smem double buffer, plain fp16).
// smem stage: A @0 (10240 B), B @10240. Stage 20480, total 40960.
// ===========================================================================
#define GSTRIDE 80
#define PANEL   10240
#define STAGE   20480
#define GEMM_SMEM (2 * STAGE)
#define KCH 16

__device__ __forceinline__ void cvt_sts(char* smc, uint32_t off, float4 v) {
    *(uint2*)(smc + off) = make_uint2(pack2h(v.x, v.y), pack2h(v.z, v.w));
}

// one 32-K chunk of fp16 MMAs for this warp
__device__ __forceinline__ void gemm_chunk(uint32_t stg, int warp_m, int warp_n,
                                           int ln, float acc[2][8][4])
{
    const uint32_t aoff = (uint32_t)((ln & 15) * GSTRIDE + (ln >> 4) * 16);
    const uint32_t boff = (uint32_t)(((ln & 7) + ((ln >> 4) << 3)) * GSTRIDE
                                     + (((ln >> 3) & 1) << 4));
    #pragma unroll
    for (int ks = 0; ks < 2; ks++) {
        uint32_t ah[2][4];
        #pragma unroll
        for (int mb = 0; mb < 2; mb++)
            ldsm4(ah[mb], stg + (uint32_t)((warp_m * 32 + mb * 16) * GSTRIDE + ks * 32) + aoff);
        #pragma unroll
        for (int nb = 0; nb < 4; nb++) {
            uint32_t bh_[4];
            ldsm4(bh_, stg + PANEL
                       + (uint32_t)((warp_n * 64 + nb * 16) * GSTRIDE + ks * 32) + boff);
            #pragma unroll
            for (int mb = 0; mb < 2; mb++) {
                mma_f16(acc[mb][2 * nb],     ah[mb], bh_[0], bh_[1]);
                mma_f16(acc[mb][2 * nb + 1], ah[mb], bh_[2], bh_[3]);
            }
        }
    }
}

// ---------------------------------------------------------------------------
// QKV projection on tensor cores -> fp16 head layout.
// ---------------------------------------------------------------------------
__global__ __launch_bounds__(256) void proj_mma_kernel(
    const float* __restrict__ Xq, const float* __restrict__ Xk, const float* __restrict__ Xv,
    const float* __restrict__ Wq, const float* __restrict__ Wk, const float* __restrict__ Wv,
    const float* __restrict__ bq, const float* __restrict__ bk, const float* __restrict__ bv)
{
    extern __shared__ char smc[];
    const uint32_t sbase = smem_u32(smc);

    const float *X, *W, *bias;
    __half* Y;
    if (blockIdx.z == 0)      { X = Xq; W = Wq; bias = bq; Y = g_q; }
    else if (blockIdx.z == 1) { X = Xk; W = Wk; bias = bk; Y = g_k; }
    else                      { X = Xv; W = Wv; bias = bv; Y = g_v; }

    const int t   = threadIdx.x;
    const int wid = t >> 5;
    const int ln  = t & 31;
    const int warp_m = wid >> 1;
    const int warp_n = wid & 1;
    const int m0 = blockIdx.x * 128;
    const int n0 = blockIdx.y * 128;

    int lrow[4], lcg[4];
    #pragma unroll
    for (int r = 0; r < 4; r++) {
        int idx = t + r * 256;
        lrow[r] = idx >> 3;
        lcg[r]  = idx & 7;
    }

    float acc[2][8][4] = {};
    float4 ra[4], rb[4];

    #pragma unroll
    for (int r = 0; r < 4; r++) {
        ra[r] = *(const float4*)(X + (size_t)(m0 + lrow[r]) * D_ + lcg[r] * 4);
        rb[r] = *(const float4*)(W + (size_t)(n0 + lrow[r]) * D_ + lcg[r] * 4);
    }
    #pragma unroll
    for (int r = 0; r < 4; r++) {
        uint32_t o = (uint32_t)(lrow[r] * GSTRIDE + lcg[r] * 8);
        cvt_sts(smc, o, ra[r]);
        cvt_sts(smc, PANEL + o, rb[r]);
    }
    __syncthreads();

    for (int p = 0; p < KCH; p++) {
        const int s = p & 1;
        if (p < KCH - 1) {
            const int k0 = (p + 1) * 32;
            #pragma unroll
            for (int r = 0; r < 4; r++) {
                ra[r] = *(const float4*)(X + (size_t)(m0 + lrow[r]) * D_ + k0 + lcg[r] * 4);
                rb[r] = *(const float4*)(W + (size_t)(n0 + lrow[r]) * D_ + k0 + lcg[r] * 4);
            }
        }
        gemm_chunk(sbase + (uint32_t)s * STAGE, warp_m, warp_n, ln, acc);
        if (p < KCH - 1) {
            const uint32_t so = (uint32_t)(s ^ 1) * STAGE;
            #pragma unroll
            for (int r = 0; r < 4; r++) {
                uint32_t o = so + (uint32_t)(lrow[r] * GSTRIDE + lcg[r] * 8);
                cvt_sts(smc, o, ra[r]);
                cvt_sts(smc, PANEL + o, rb[r]);
            }
        }
        __syncthreads();
    }

    const int g  = ln >> 2;
    const int tq = ln & 3;
    #pragma unroll
    for (int mb = 0; mb < 2; mb++) {
        int r0 = m0 + warp_m * 32 + mb * 16 + g;
        int r1 = r0 + 8;
        int bb0 = r0 >> 11, ll0 = r0 & (L_ - 1);
        int bb1 = r1 >> 11, ll1 = r1 & (L_ - 1);
        #pragma unroll
        for (int f = 0; f < 8; f++) {
            int col = n0 + warp_n * 64 + f * 8 + 2 * tq;
            int hh = col >> 6, dh = col & 63;
            float b0 = bias[col], b1 = bias[col + 1];
            size_t o0 = (((size_t)bb0 * H_ + hh) * L_ + ll0) * DH_ + dh;
            *(uint32_t*)(Y + o0) = pack2h(acc[mb][f][0] + b0, acc[mb][f][1] + b1);
            size_t o1 = (((size_t)bb1 * H_ + hh) * L_ + ll1) * DH_ + dh;
            *(uint32_t*)(Y + o1) = pack2h(acc[mb][f][2] + b0, acc[mb][f][3] + b1);
        }
    }
}

// ---------------------------------------------------------------------------
// Output projection: gathers fp16 (B,H,L,DH) rows from g_oh -> fp32 out.
// ---------------------------------------------------------------------------
__global__ __launch_bounds__(256) void fc_mma_kernel(
    const float* __restrict__ Wf, const float* __restrict__ bf, float* __restrict__ out)
{
    extern __shared__ char smc[];
    const uint32_t sbase = smem_u32(smc);

    const int t   = threadIdx.x;
    const int wid = t >> 5;
    const int ln  = t & 31;
    const int warp_m = wid >> 1;
    const int warp_n = wid & 1;
    const int m0 = blockIdx.x * 128;
    const int n0 = blockIdx.y * 128;

    int lrow[4], lcg[4], lbb[4], lll[4];
    #pragma unroll
    for (int r = 0; r < 4; r++) {
        int idx = t + r * 256;
        lrow[r] = idx >> 3;
        lcg[r]  = idx & 7;
        int n = m0 + lrow[r];
        lbb[r] = n >> 11;
        lll[r] = n & (L_ - 1);
    }

    float acc[2][8][4] = {};
    uint2 ra[4];
    float4 rb[4];

    auto loadA = [&](int r, int k0) -> uint2 {
        int d  = k0 + lcg[r] * 4;
        int hh = d >> 6, dh = d & 63;
        return *(const uint2*)(g_oh + (((size_t)lbb[r] * H_ + hh) * L_ + lll[r]) * DH_ + dh);
    };

    #pragma unroll
    for (int r = 0; r < 4; r++) {
        ra[r] = loadA(r, 0);
        rb[r] = *(const float4*)(Wf + (size_t)(n0 + lrow[r]) * D_ + lcg[r] * 4);
    }
    #pragma unroll
    for (int r = 0; r < 4; r++) {
        uint32_t o = (uint32_t)(lrow[r] * GSTRIDE + lcg[r] * 8);
        *(uint2*)(smc + o) = ra[r];
        cvt_sts(smc, PANEL + o, rb[r]);
    }
    __syncthreads();

    for (int p = 0; p < KCH; p++) {
        const int s = p & 1;
        if (p < KCH - 1) {
            const int k0 = (p + 1) * 32;
            #pragma unroll
            for (int r = 0; r < 4; r++) {
                ra[r] = loadA(r, k0);
                rb[r] = *(const float4*)(Wf + (size_t)(n0 + lrow[r]) * D_ + k0 + lcg[r] * 4);
            }
        }
        gemm_chunk(sbase + (uint32_t)s * STAGE, warp_m, warp_n, ln, acc);
        if (p < KCH - 1) {
            const uint32_t so = (uint32_t)(s ^ 1) * STAGE;
            #pragma unroll
            for (int r = 0; r < 4; r++) {
                uint32_t o = so + (uint32_t)(lrow[r] * GSTRIDE + lcg[r] * 8);
                *(uint2*)(smc + o) = ra[r];
                cvt_sts(smc, PANEL + o, rb[r]);
            }
        }
        __syncthreads();
    }

    const int g  = ln >> 2;
    const int tq = ln & 3;
    #pragma unroll
    for (int mb = 0; mb < 2; mb++) {
        int r0 = m0 + warp_m * 32 + mb * 16 + g;
        int r1 = r0 + 8;
        #pragma unroll
        for (int f = 0; f < 8; f++) {
            int col = n0 + warp_n * 64 + f * 8 + 2 * tq;
            float b0 = bf[col], b1 = bf[col + 1];
            *(float2*)(out + (size_t)r0 * D_ + col) =
                make_float2(acc[mb][f][0] + b0, acc[mb][f][1] + b1);
            *(float2*)(out + (size_t)r1 * D_ + col) =
                make_float2(acc[mb][f][2] + b0, acc[mb][f][3] + b1);
        }
    }
}

// ===========================================================================
// Attention: flash-style causal + rel-pos, plain fp16 mma.sync.
// 128 threads (4 warps); warp w owns q rows [w*16, w*16+16).
// smem: PanA fp32 64x68 @0 (Q fp16 aliases in prologue) | PanB @17408 |
//       WORK fp16 64x72 @34816.  Total 44032 B.
// ===========================================================================
#define PAN_A   0
#define PAN_B   17408
#define QH_OFF  0
#define WORK_H  34816
#define ATTN_SMEM 44032
#define TSTRIDE 144   // bytes per smem tile row (72 fp16)
#define SCL 0.18033688011112042f   // 0.125 * log2(e)

__device__ __forceinline__ void load_tile(char* smc, int woff,
    const __half* __restrict__ src, int rowbase, int t, int clampE)
{
    #pragma unroll
    for (int r = 0; r < 4; r++) {
        int idx = t + r * 128;
        int row = idx >> 3, c8 = idx & 7;
        int gr = rowbase + row;
        if (clampE) gr = (gr < L_) ? gr : (L_ - 1);
        *(uint4*)(smc + woff + row * TSTRIDE + c8 * 16) =
            *(const uint4*)(src + (size_t)gr * DH_ + c8 * 8);
    }
}

// acc[8][4] = Qwarp(16 x 64) * tile(64 x 64)^T, plain fp16
__device__ __forceinline__ void gemm_tile(float acc[8][4],
    const uint32_t qf[4][4], uint32_t th, uint32_t boff)
{
    #pragma unroll
    for (int f = 0; f < 8; f++)
        #pragma unroll
        for (int c = 0; c < 4; c++) acc[f][c] = 0.f;
    #pragma unroll
    for (int kc = 0; kc < 4; kc++) {
        #pragma unroll
        for (int nbp = 0; nbp < 4; nbp++) {
            uint32_t bh_[4];
            ldsm4(bh_, th + (uint32_t)(nbp * 16 * TSTRIDE + kc * 32) + boff);
            mma_f16(acc[2 * nbp],     qf[kc], bh_[0], bh_[1]);
            mma_f16(acc[2 * nbp + 1], qf[kc], bh_[2], bh_[3]);
        }
    }
}

__device__ __forceinline__ void store_panel(float* pan, const float acc[8][4],
                                            int prow, int tq)
{
    #pragma unroll
    for (int f = 0; f < 8; f++) {
        *(float2*)&pan[prow * 68 + 8 * f + 2 * tq]       = make_float2(acc[f][0], acc[f][1]);
        *(float2*)&pan[(prow + 8) * 68 + 8 * f + 2 * tq] = make_float2(acc[f][2], acc[f][3]);
    }
}

__global__ __launch_bounds__(128) void attn_kernel()
{
    extern __shared__ char smc[];
    const uint32_t sbase = smem_u32(smc);
    float* PanAp = (float*)(smc + PAN_A);
    float* PanBp = (float*)(smc + PAN_B);

    const int t  = threadIdx.x;
    const int w  = t >> 5;
    const int ln = t & 31;
    const int g  = ln >> 2;
    const int tq = ln & 3;
    const int qt = (int)(gridDim.x - 1) - (int)blockIdx.x;  // heavy first
    const int l0 = qt * 64;
    const int bh = blockIdx.y;

    const size_t hoff = (size_t)bh * L_ * DH_;

    const uint32_t aoff = (uint32_t)((w * 16 + (ln & 15)) * TSTRIDE + (ln >> 4) * 16);
    const uint32_t boff = (uint32_t)(((ln & 7) + ((ln >> 4) << 3)) * TSTRIDE + (((ln >> 3) & 1) << 4));
    const uint32_t voff = (uint32_t)(((ln & 7) + (((ln >> 3) & 1) << 3)) * TSTRIDE + ((ln >> 4) << 4));

    // prologue: Q tile (aliases panel space), E tile into WORK
    load_tile(smc, QH_OFF, g_q + hoff, l0, t, 0);
    const int jb = L_ - 64 - l0;
    load_tile(smc, WORK_H, g_e, jb, t, 0);
    __syncthreads();

    uint32_t qf[4][4];
    #pragma unroll
    for (int kc = 0; kc < 4; kc++)
        ldsm4(qf[kc], sbase + QH_OFF + kc * 32 + aoff);
    __syncthreads();   // Q smem dead; panels writable

    float acc[8][4];
    gemm_tile(acc, qf, sbase + WORK_H, boff);
    store_panel(PanAp, acc, w * 16 + g, tq);

    float* plo = PanAp;
    float* phi = PanBp;

    float Oa[8][4] = {};
    float rm0 = -1e30f, rm1 = -1e30f, rl0 = 0.f, rl1 = 0.f;

    const int rt0 = w * 16 + g;
    const int rt1 = rt0 + 8;
    const int ntiles = qt + 1;

    for (int tt = 0; tt < ntiles; tt++) {
        const int m0k = tt * 64;

        __syncthreads();
        load_tile(smc, WORK_H, g_e, jb + 64 * (tt + 1), t, 1);
        __syncthreads();

        gemm_tile(acc, qf, sbase + WORK_H, boff);
        store_panel(phi, acc, rt0, tq);
        __syncthreads();

        load_tile(smc, WORK_H, g_k + hoff, m0k, t, 0);
        __syncthreads();

        gemm_tile(acc, qf, sbase + WORK_H, boff);

        // rel-pos gather + log2-domain scale + causal mask
        #pragma unroll
        for (int f = 0; f < 8; f++) {
            int mi = 8 * f + 2 * tq;
            #pragma unroll
            for (int c = 0; c < 2; c++) {
                int cc = 63 - rt0 + mi + c;
                float rel = (cc < 64) ? plo[rt0 * 68 + cc] : phi[rt0 * 68 + cc - 64];
                float sv  = (acc[f][c] + rel) * SCL;
                acc[f][c] = (m0k + mi + c <= l0 + rt0) ? sv : -1e30f;
            }
            #pragma unroll
            for (int c = 0; c < 2; c++) {
                int cc = 63 - rt1 + mi + c;
                float rel = (cc < 64) ? plo[rt1 * 68 + cc] : phi[rt1 * 68 + cc - 64];
                float sv  = (acc[f][2 + c] + rel) * SCL;
                acc[f][2 + c] = (m0k + mi + c <= l0 + rt1) ? sv : -1e30f;
            }
        }
        __syncthreads();

        load_tile(smc, WORK_H, g_v + hoff, m0k, t, 0);

        // online softmax in log2 domain
        float mx0 = -1e30f, mx1 = -1e30f;
        #pragma unroll
        for (int f = 0; f < 8; f++) {
            mx0 = fmaxf(mx0, fmaxf(acc[f][0], acc[f][1]));
            mx1 = fmaxf(mx1, fmaxf(acc[f][2], acc[f][3]));
        }
        mx0 = fmaxf(mx0, __shfl_xor_sync(0xffffffffu, mx0, 1));
        mx0 = fmaxf(mx0, __shfl_xor_sync(0xffffffffu, mx0, 2));
        mx1 = fmaxf(mx1, __shfl_xor_sync(0xffffffffu, mx1, 1));
        mx1 = fmaxf(mx1, __shfl_xor_sync(0xffffffffu, mx1, 2));
        float mn0 = fmaxf(rm0, mx0), mn1 = fmaxf(rm1, mx1);
        float cr0 = fex2(rm0 - mn0), cr1 = fex2(rm1 - mn1);
        float s0 = 0.f, s1 = 0.f;
        #pragma unroll
        for (int f = 0; f < 8; f++) {
            acc[f][0] = fex2(acc[f][0] - mn0); s0 += acc[f][0];
            acc[f][1] = fex2(acc[f][1] - mn0); s0 += acc[f][1];
            acc[f][2] = fex2(acc[f][2] - mn1); s1 += acc[f][2];
            acc[f][3] = fex2(acc[f][3] - mn1); s1 += acc[f][3];
        }
        s0 += __shfl_xor_sync(0xffffffffu, s0, 1);
        s0 += __shfl_xor_sync(0xffffffffu, s0, 2);
        s1 += __shfl_xor_sync(0xffffffffu, s1, 1);
        s1 += __shfl_xor_sync(0xffffffffu, s1, 2);
        rl0 = rl0 * cr0 + s0; rm0 = mn0;
        rl1 = rl1 * cr1 + s1; rm1 = mn1;
        #pragma unroll
        for (int f = 0; f < 8; f++) {
            Oa[f][0] *= cr0; Oa[f][1] *= cr0;
            Oa[f][2] *= cr1; Oa[f][3] *= cr1;
        }
        __syncthreads();   // V visible

        // O += P @ V, P packed to fp16 A-fragments in registers
        #pragma unroll
        for (int kc = 0; kc < 4; kc++) {
            uint32_t pha[4];
            pha[0] = pack2h(acc[2 * kc][0],     acc[2 * kc][1]);
            pha[1] = pack2h(acc[2 * kc][2],     acc[2 * kc][3]);
            pha[2] = pack2h(acc[2 * kc + 1][0], acc[2 * kc + 1][1]);
            pha[3] = pack2h(acc[2 * kc + 1][2], acc[2 * kc + 1][3]);
            #pragma unroll
            for (int nb = 0; nb < 4; nb++) {
                uint32_t vh_[4];
                ldsm4t(vh_, sbase + WORK_H + (uint32_t)(kc * 16 * TSTRIDE + nb * 32) + voff);
                mma_f16(Oa[2 * nb],     pha, vh_[0], vh_[1]);
                mma_f16(Oa[2 * nb + 1], pha, vh_[2], vh_[3]);
            }
        }

        float* tmp = plo; plo = phi; phi = tmp;
    }

    // epilogue: fp16 output (fc rounds to fp16 anyway)
    float inv0 = 1.0f / rl0, inv1 = 1.0f / rl1;
    __half* op = g_oh + hoff;
    #pragma unroll
    for (int f = 0; f < 8; f++) {
        int col = 8 * f + 2 * tq;
        *(uint32_t*)(op + (size_t)(l0 + rt0) * DH_ + col) =
            pack2h(Oa[f][0] * inv0, Oa[f][1] * inv0);
        *(uint32_t*)(op + (size_t)(l0 + rt1) * DH_ + col) =
            pack2h(Oa[f][2] * inv1, Oa[f][3] * inv1);
    }
}

// ---------------------------------------------------------------------------
extern "C" void kernel_launch(void* const* d_in, const int* in_sizes, int n_in,
                              void* d_out, int out_size)
{
    const float* Q  = (const float*)d_in[0];
    const float* K  = (const float*)d_in[1];
    const float* V  = (const float*)d_in[2];
    // d_in[3] = mask (causal, known analytically) - unused
    const float* Wq = (const float*)d_in[4];
    const float* bq = (const float*)d_in[5];
    const float* Wk = (const float*)d_in[6];
    const float* bk = (const float*)d_in[7];
    const float* Wv = (const float*)d_in[8];
    const float* bv = (const float*)d_in[9];
    const float* Wf = (const float*)d_in[10];
    const float* bf = (const float*)d_in[11];
    const float* E  = (const float*)d_in[12];
    // d_in[13] = H (known constant 8) - unused
    float* out = (float*)d_out;

    (void)in_sizes; (void)n_in; (void)out_size;

    eprep_kernel<<<(L_ * DH_ + 255) / 256, 256>>>(E);

    cudaFuncSetAttribute(proj_mma_kernel, cudaFuncAttributeMaxDynamicSharedMemorySize,
                         GEMM_SMEM);
    cudaFuncSetAttribute(fc_mma_kernel, cudaFuncAttributeMaxDynamicSharedMemorySize,
                         GEMM_SMEM);
    cudaFuncSetAttribute(attn_kernel, cudaFuncAttributeMaxDynamicSharedMemorySize,
                         ATTN_SMEM);

    dim3 gproj(NTOK / 128, D_ / 128, 3);
    proj_mma_kernel<<<gproj, 256, GEMM_SMEM>>>(Q, K, V, Wq, Wk, Wv, bq, bk, bv);

    dim3 gattn(L_ / 64, B_ * H_);
    attn_kernel<<<gattn, 128, ATTN_SMEM>>>();

    dim3 gfc(NTOK / 128, D_ / 128);
    fc_mma_kernel<<<gfc, 256, GEMM_SMEM>>>(Wf, bf, out);
}